// round 12
// baseline (speedup 1.0000x reference)
#include <cuda_runtime.h>
#include <cuda_bf16.h>
#include <math.h>
#include <stdint.h>

// Problem constants
#define NN    4096
#define DD    64
#define HH    4
#define OO    64
#define KK    2
#define KHT   8        // K*H
#define NUSER 4000
#define CC    2
#define NW32  (NN / 32)                 // mask words per row = 128
#define TOTAL_WORDS (KK * NN * NW32)    // 1,048,576

// Device scratch (allocation-free rule: static __device__ arrays)
__device__ __nv_bfloat16 g_hpT[KHT * OO * NN];   // h_prime transposed [kh][o][m] bf16 (4 MB)
__device__ float         g_att[KHT * NN * OO];   // attention output per (k,h)  (8 MB)
__device__ uint32_t      g_mask[TOTAL_WORDS];    // adjacency bitmask (4 MB)
__device__ float g_thr [KHT * NN];       // -src[n]
__device__ float g_es1 [KHT * NN];       // exp(src)
__device__ float g_es2 [KHT * NN];       // exp(0.2*src)
__device__ float g_dstv[KHT * NN];       // dst[m]
__device__ float g_ed1 [KHT * NN];       // exp(dst)
__device__ float g_ed2 [KHT * NN];       // exp(0.2*dst)

// ---------------------------------------------------------------------------
// Arch-agnostic tensor-core helpers (generic PTX, works on compute_103)
// ---------------------------------------------------------------------------
__device__ __forceinline__ uint32_t smem_u32(const void* p) {
    uint32_t a;
    asm("{ .reg .u64 t; cvta.to.shared.u64 t, %1; cvt.u32.u64 %0, t; }" : "=r"(a) : "l"(p));
    return a;
}
__device__ __forceinline__ void ldsm_x4(uint32_t* r, uint32_t addr) {
    asm volatile("ldmatrix.sync.aligned.m8n8.x4.shared.b16 {%0,%1,%2,%3}, [%4];"
        : "=r"(r[0]), "=r"(r[1]), "=r"(r[2]), "=r"(r[3]) : "r"(addr));
}
__device__ __forceinline__ void mma16816(float* c, const uint32_t* a, const uint32_t* b) {
    asm volatile("mma.sync.aligned.m16n8k16.row.col.f32.bf16.bf16.f32 "
        "{%0,%1,%2,%3}, {%4,%5,%6,%7}, {%8,%9}, {%0,%1,%2,%3};"
        : "+f"(c[0]), "+f"(c[1]), "+f"(c[2]), "+f"(c[3])
        : "r"(a[0]), "r"(a[1]), "r"(a[2]), "r"(a[3]), "r"(b[0]), "r"(b[1]));
}

// ---------------------------------------------------------------------------
// Kernel 1 (fused): h_prime = h @ w  ->  bf16 transposed copy (MMA B operand)
//                   + tanh / a_src / a_dst dots + factorized exponentials
//                   + adjacency bitmask pack (grid-stride epilogue, overlaps).
// grid (N/64, KH), 256 threads.
// ---------------------------------------------------------------------------
__global__ void k_hproj(const float* __restrict__ h, const float* __restrict__ w,
                        const float* __restrict__ a_src, const float* __restrict__ a_dst,
                        const float* __restrict__ adj) {
    const int kh = blockIdx.y;
    const int n0 = blockIdx.x * 64;
    __shared__ float shT[64][68];     // [d][i]  (transposed h tile)
    __shared__ float buf[64 * 68];    // first 4096 floats: w tile; reused as [o][n] (stride 68)
    __shared__ float sa[128];         // a_src[kh][o], a_dst[kh][o]
    const int tid = threadIdx.x;

    if (tid < 64) {
        sa[tid]      = a_src[kh * 64 + tid];
        sa[64 + tid] = a_dst[kh * 64 + tid];
    }

    const float4* wkh = (const float4*)(w + (size_t)kh * 64 * 64);
    #pragma unroll
    for (int it = 0; it < 4; it++) ((float4*)buf)[tid + it * 256] = wkh[tid + it * 256];

    {
        const int d = tid & 63, ig0 = tid >> 6;
        #pragma unroll
        for (int it = 0; it < 4; it++) {
            const int ig = ig0 + it * 4;
            float4 v;
            v.x = h[(size_t)(n0 + ig * 4 + 0) * DD + d];
            v.y = h[(size_t)(n0 + ig * 4 + 1) * DD + d];
            v.z = h[(size_t)(n0 + ig * 4 + 2) * DD + d];
            v.w = h[(size_t)(n0 + ig * 4 + 3) * DD + d];
            *(float4*)&shT[d][ig * 4] = v;
        }
    }
    __syncthreads();

    const int ty = tid >> 4, tx = tid & 15;
    float acc[4][4] = {};
    #pragma unroll 8
    for (int j = 0; j < 64; j++) {
        const float4 pv = *(const float4*)&shT[j][ty * 4];
        const float4 hv = *(const float4*)&buf[j * 64 + tx * 4];
        acc[0][0] += pv.x * hv.x; acc[0][1] += pv.x * hv.y; acc[0][2] += pv.x * hv.z; acc[0][3] += pv.x * hv.w;
        acc[1][0] += pv.y * hv.x; acc[1][1] += pv.y * hv.y; acc[1][2] += pv.y * hv.z; acc[1][3] += pv.y * hv.w;
        acc[2][0] += pv.z * hv.x; acc[2][1] += pv.z * hv.y; acc[2][2] += pv.z * hv.z; acc[2][3] += pv.z * hv.w;
        acc[3][0] += pv.w * hv.x; acc[3][1] += pv.w * hv.y; acc[3][2] += pv.w * hv.z; acc[3][3] += pv.w * hv.w;
    }

    // ---- fused attvec: per-row tanh-dot partials, reduce across tx ----
    {
        float pas[4] = {}, pad[4] = {};
        #pragma unroll
        for (int r = 0; r < 4; r++)
            #pragma unroll
            for (int c = 0; c < 4; c++) {
                const float t = tanhf(acc[r][c]);
                pas[r] += t * sa[tx * 4 + c];
                pad[r] += t * sa[64 + tx * 4 + c];
            }
        #pragma unroll
        for (int off = 1; off < 16; off <<= 1)
            #pragma unroll
            for (int r = 0; r < 4; r++) {
                pas[r] += __shfl_xor_sync(0xFFFFFFFFu, pas[r], off);
                pad[r] += __shfl_xor_sync(0xFFFFFFFFu, pad[r], off);
            }
        if (tx == 0) {
            #pragma unroll
            for (int r = 0; r < 4; r++) {
                const int idx = kh * NN + n0 + ty * 4 + r;
                const float as = pas[r], ad = pad[r];
                g_thr [idx] = -as;
                g_es1 [idx] = expf(as);
                g_es2 [idx] = expf(0.2f * as);
                g_dstv[idx] = ad;
                g_ed1 [idx] = expf(ad);
                g_ed2 [idx] = expf(0.2f * ad);
            }
        }
    }

    __syncthreads();            // done reading buf as w-tile
    // transpose into buf as [o][n_local], stride 68 to avoid conflicts
    #pragma unroll
    for (int r = 0; r < 4; r++)
        #pragma unroll
        for (int c = 0; c < 4; c++)
            buf[(tx * 4 + c) * 68 + ty * 4 + r] = acc[r][c];
    __syncthreads();
    // write bf16 transposed rows: thread -> row o = tid>>2, 16 n values
    {
        const int o = tid >> 2, nc = (tid & 3) * 16;
        __nv_bfloat162 tmp[8];
        #pragma unroll
        for (int j = 0; j < 8; j++)
            tmp[j] = __floats2bfloat162_rn(buf[o * 68 + nc + 2 * j], buf[o * 68 + nc + 2 * j + 1]);
        __nv_bfloat16* dst = g_hpT + ((size_t)kh * 64 + o) * NN + n0 + nc;
        *(uint4*)dst       = ((uint4*)tmp)[0];
        *(uint4*)(dst + 8) = ((uint4*)tmp)[1];
    }

    // ---- adjacency bitmask pack (grid-stride; overlaps across CTAs) ----
    {
        const int lane = tid & 31;
        const int gw   = ((blockIdx.y * gridDim.x + blockIdx.x) * 256 + tid) >> 5;
        const int nwarps = (gridDim.x * gridDim.y * 256) >> 5;   // 4096
        for (int wd = gw; wd < TOTAL_WORDS; wd += nwarps) {
            const float v = adj[(size_t)wd * 32 + lane];
            const uint32_t b = __ballot_sync(0xFFFFFFFFu, v != 0.0f);
            if (lane == 0) g_mask[wd] = b;
        }
    }
}

// ---------------------------------------------------------------------------
// Kernel 2 (dominant, mma.sync bf16): ONE head per CTA, bitmask adjacency
// (L2-resident), DOUBLE-BUFFERED P/B smem (1 sync per chunk), prefetch
// issued BEFORE the barrier so LDG latency hides under sync-wait + mma.
//   D[128,64] += P[128,64]_bf16 @ HpT[64(o),64(m)]_bf16^T   (chunks over m)
//   P[n,m] = bit(k,n,m) * (dst[m] >= -src[n] ? es1[n]*ed1[m] : es2[n]*ed2[m])
// grid (N/128=32, K=2, H=4), 256 threads (8 warps), dynamic smem 56KB.
// ---------------------------------------------------------------------------
#define P_OFF   0
#define PH_B    18432
#define B_OFF   36864
#define BH_B    9216
#define RC_OFF  55296
#define D_OFF   56832
#define SMEM_DYN 57344

__global__ void __launch_bounds__(256, 2) k_main8() {
    extern __shared__ char sm[];
    const uint32_t smb = smem_u32(sm);
    const int tid  = threadIdx.x;
    const int wid  = tid >> 5;
    const int lane = tid & 31;
    const int k    = blockIdx.y;
    const int hh   = blockIdx.z;
    const int n0   = blockIdx.x * 128;
    const int kh   = k * HH + hh;

    // stage row-side constants into smem
    if (tid < 128) {
        const int ridx = kh * NN + n0 + tid;
        ((float*)(sm + RC_OFF))[tid]       = g_thr[ridx];
        ((float*)(sm + RC_OFF))[128 + tid] = g_es1[ridx];
        ((float*)(sm + RC_OFF))[256 + tid] = g_es2[ridx];
    }

    // P-build mapping: fixed cols, walk rows
    const int g     = tid >> 4;          // 0..15
    const int cbase = (tid & 15) * 4;    // 0..60
    const int wsel  = cbase >> 5;
    const int shift = cbase & 31;
    const uint32_t* mrow = g_mask + (size_t)k * NN * NW32 + (size_t)(n0 + g) * NW32 + wsel;
    const float* mdv = g_dstv + kh * NN;
    const float* me1 = g_ed1  + kh * NN;
    const float* me2 = g_ed2  + kh * NN;

    // B tile load mapping: 64 rows x 64 bf16 = 512 uint4, 2 per thread
    const int brow0 = tid >> 3,          bcol0 = tid & 7;
    const int brow1 = (tid + 256) >> 3,  bcol1 = tid & 7;
    const __nv_bfloat16* hptk = g_hpT + (size_t)kh * 64 * NN;

    // mma warp mapping: warp -> (row slab = wid&3, o-half = wid>>2)
    const int slab  = wid & 3;
    const int ohalf = wid >> 2;
    const int mbase = slab * 32;
    const int a_row = ((lane >> 3) & 1) * 8 + (lane & 7);
    const int a_k   = (lane >> 4) * 8;
    const uint32_t aAddr = smb + P_OFF + (mbase + a_row) * 144 + a_k * 2;
    const int b_n = ((lane >> 4) & 1) * 8 + (lane & 7);
    const int b_k = ((lane >> 3) & 1) * 8;
    const uint32_t bAddr = smb + B_OFF + (ohalf * 32 + b_n) * 144 + b_k * 2;

    float acc[2][4][4];     // [row 16-slab][o-frag][c]
    #pragma unroll
    for (int a = 0; a < 2; a++)
        #pragma unroll
        for (int b = 0; b < 4; b++)
            #pragma unroll
            for (int cc = 0; cc < 4; cc++) acc[a][b][cc] = 0.0f;
    float den[8];
    #pragma unroll
    for (int j = 0; j < 8; j++) den[j] = 0.0f;

    const float* sthr = (const float*)(sm + RC_OFF);

    // ---- prefetch chunk 0 ----
    uint32_t mw[8];
    uint4  bq0, bq1;
    float4 dv4, q14, q24;
    {
        #pragma unroll
        for (int j = 0; j < 8; j++)
            mw[j] = mrow[(size_t)(j * 16) * NW32];
        bq0 = *(const uint4*)(hptk + (size_t)brow0 * NN + bcol0 * 8);
        bq1 = *(const uint4*)(hptk + (size_t)brow1 * NN + bcol1 * 8);
        dv4 = *(const float4*)(mdv + cbase);
        q14 = *(const float4*)(me1 + cbase);
        q24 = *(const float4*)(me2 + cbase);
    }
    __syncthreads();   // row consts visible

    for (int c = 0; c < NN / 64; c++) {
        const int buf = c & 1;

        // ---- stage B (from prefetched regs) ----
        *(uint4*)(sm + B_OFF + buf * BH_B + brow0 * 144 + bcol0 * 16) = bq0;
        *(uint4*)(sm + B_OFF + buf * BH_B + brow1 * 144 + bcol1 * 16) = bq1;

        // ---- build P tile (bf16): 8 rows x 4 cols per thread ----
        #pragma unroll
        for (int j = 0; j < 8; j++) {
            const int row = g + j * 16;
            const float thr = sthr[row];
            const float e1  = sthr[128 + row];
            const float e2  = sthr[256 + row];
            const uint32_t bits = mw[j] >> shift;
            const float v0 = (dv4.x >= thr) ? e1 * q14.x : e2 * q24.x;
            const float v1 = (dv4.y >= thr) ? e1 * q14.y : e2 * q24.y;
            const float v2 = (dv4.z >= thr) ? e1 * q14.z : e2 * q24.z;
            const float v3 = (dv4.w >= thr) ? e1 * q14.w : e2 * q24.w;
            const float p0 = (bits & 1u) ? v0 : 0.0f;
            const float p1 = (bits & 2u) ? v1 : 0.0f;
            const float p2 = (bits & 4u) ? v2 : 0.0f;
            const float p3 = (bits & 8u) ? v3 : 0.0f;
            den[j] += (p0 + p1) + (p2 + p3);
            __nv_bfloat162 lo = __floats2bfloat162_rn(p0, p1);
            __nv_bfloat162 hi = __floats2bfloat162_rn(p2, p3);
            uint2 v;
            v.x = *(uint32_t*)&lo;
            v.y = *(uint32_t*)&hi;
            *(uint2*)(sm + P_OFF + buf * PH_B + row * 144 + cbase * 2) = v;
        }

        // ---- prefetch chunk c+1 BEFORE the barrier (flies under sync+mma) ----
        if (c < NN / 64 - 1) {
            const int mt = (c + 1) << 6;
            #pragma unroll
            for (int j = 0; j < 8; j++)
                mw[j] = mrow[(size_t)(j * 16) * NW32 + (mt >> 5)];
            bq0 = *(const uint4*)(hptk + (size_t)brow0 * NN + mt + bcol0 * 8);
            bq1 = *(const uint4*)(hptk + (size_t)brow1 * NN + mt + bcol1 * 8);
            dv4 = *(const float4*)(mdv + mt + cbase);
            q14 = *(const float4*)(me1 + mt + cbase);
            q24 = *(const float4*)(me2 + mt + cbase);
        }

        __syncthreads();   // this chunk's P + B visible; prior chunk's mma reads done

        // ---- tensor cores: 32 x m16n8k16 per warp ----
        const uint32_t aB = aAddr + buf * PH_B;
        const uint32_t bB = bAddr + buf * BH_B;
        #pragma unroll
        for (int ks = 0; ks < 4; ks++) {
            uint32_t af0[4], af1[4];
            ldsm_x4(af0, aB + ks * 32);
            ldsm_x4(af1, aB + 16 * 144 + ks * 32);
            #pragma unroll
            for (int nt = 0; nt < 2; nt++) {
                uint32_t bf[4];
                ldsm_x4(bf, bB + nt * (16 * 144) + ks * 32);
                mma16816(acc[0][2 * nt],     af0, bf);
                mma16816(acc[0][2 * nt + 1], af0, bf + 2);
                mma16816(acc[1][2 * nt],     af1, bf);
                mma16816(acc[1][2 * nt + 1], af1, bf + 2);
            }
        }
    }

    // ---- denominator reduce: 16 col-owner lanes per row ----
    #pragma unroll
    for (int j = 0; j < 8; j++) {
        float v = den[j];
        v += __shfl_xor_sync(0xFFFFFFFFu, v, 8);
        v += __shfl_xor_sync(0xFFFFFFFFu, v, 4);
        v += __shfl_xor_sync(0xFFFFFFFFu, v, 2);
        v += __shfl_xor_sync(0xFFFFFFFFu, v, 1);
        if ((tid & 15) == 0)
            ((float*)(sm + D_OFF))[g + j * 16] = v;
    }
    __syncthreads();

    // ---- epilogue: scale by 1/den, store ----
    const float* sden = (const float*)(sm + D_OFF);
    #pragma unroll
    for (int mt2 = 0; mt2 < 2; mt2++) {
        const int row0 = mbase + mt2 * 16 + (lane >> 2);
        const float inv0 = 1.0f / sden[row0];
        const float inv1 = 1.0f / sden[row0 + 8];
        float* op0 = g_att + ((size_t)kh * NN + n0 + row0) * OO;
        float* op1 = op0 + 8 * OO;
        #pragma unroll
        for (int j = 0; j < 4; j++) {
            const int col = ohalf * 32 + j * 8 + (lane & 3) * 2;
            float2 v0 = make_float2(acc[mt2][j][0] * inv0, acc[mt2][j][1] * inv0);
            float2 v1 = make_float2(acc[mt2][j][2] * inv1, acc[mt2][j][3] * inv1);
            *(float2*)(op0 + col) = v0;
            *(float2*)(op1 + col) = v1;
        }
    }
}

// ---------------------------------------------------------------------------
// Kernel 3: head-mean -> concat -> fc (C=2) -> log_softmax.
// ---------------------------------------------------------------------------
__global__ void k_final(const float* __restrict__ fc_w, const float* __restrict__ fc_b,
                        float* __restrict__ out) {
    const int wg = blockIdx.x * 8 + (threadIdx.x >> 5);
    if (wg >= NUSER) return;
    const int lane = threadIdx.x & 31;
    const int n = wg;

    float l0 = 0.0f, l1 = 0.0f;
    #pragma unroll
    for (int u = 0; u < 4; u++) {
        const int d = lane + u * 32;
        const int k = d >> 6, o = d & 63;
        float e = 0.0f;
        #pragma unroll
        for (int h = 0; h < HH; h++)
            e += g_att[(((size_t)(k * HH + h) * NN) + n) * OO + o];
        e *= 0.25f;
        l0 += e * fc_w[d];
        l1 += e * fc_w[128 + d];
    }
    #pragma unroll
    for (int off = 16; off; off >>= 1) {
        l0 += __shfl_xor_sync(0xFFFFFFFFu, l0, off);
        l1 += __shfl_xor_sync(0xFFFFFFFFu, l1, off);
    }
    if (lane == 0) {
        l0 += fc_b[0];
        l1 += fc_b[1];
        const float mx  = fmaxf(l0, l1);
        const float lse = mx + logf(expf(l0 - mx) + expf(l1 - mx));
        out[n * 2 + 0] = l0 - lse;
        out[n * 2 + 1] = l1 - lse;
    }
}

// ---------------------------------------------------------------------------
extern "C" void kernel_launch(void* const* d_in, const int* in_sizes, int n_in,
                              void* d_out, int out_size) {
    (void)in_sizes; (void)n_in; (void)out_size;
    const float* h     = (const float*)d_in[0];
    const float* hadj  = (const float*)d_in[1];
    const float* w     = (const float*)d_in[2];
    const float* a_src = (const float*)d_in[3];
    const float* a_dst = (const float*)d_in[4];
    const float* fc_w  = (const float*)d_in[5];
    const float* fc_b  = (const float*)d_in[6];
    float* out = (float*)d_out;

    static int smem_set = 0;
    if (!smem_set) {
        cudaFuncSetAttribute(k_main8, cudaFuncAttributeMaxDynamicSharedMemorySize, SMEM_DYN);
        smem_set = 1;
    }

    k_hproj <<<dim3(NN / 64, KHT), 256>>>(h, w, a_src, a_dst, hadj);
    k_main8 <<<dim3(NN / 128, KK, HH), 256, SMEM_DYN>>>();
    k_final <<<NUSER / 8, 256>>>(fc_w, fc_b, out);
}

// round 13
// speedup vs baseline: 1.3551x; 1.3551x over previous
#include <cuda_runtime.h>
#include <cuda_bf16.h>
#include <math.h>
#include <stdint.h>

// Problem constants
#define NN    4096
#define DD    64
#define HH    4
#define OO    64
#define KK    2
#define KHT   8        // K*H
#define NUSER 4000
#define CC    2
#define NW32  (NN / 32)                 // mask words per row = 128
#define TOTAL_WORDS (KK * NN * NW32)    // 1,048,576

// Device scratch (allocation-free rule: static __device__ arrays)
__device__ __nv_bfloat16 g_hpT[KHT * OO * NN];   // h_prime transposed [kh][o][m] bf16 (4 MB)
__device__ float         g_att[KHT * NN * OO];   // attention output per (k,h)  (8 MB)
__device__ uint32_t      g_mask[TOTAL_WORDS];    // adjacency bitmask (4 MB)
__device__ float g_thr [KHT * NN];       // -src[n]
__device__ float g_es1 [KHT * NN];       // exp(src)
__device__ float g_es2 [KHT * NN];       // exp(0.2*src)
__device__ float g_dstv[KHT * NN];       // dst[m]
__device__ float g_ed1 [KHT * NN];       // exp(dst)
__device__ float g_ed2 [KHT * NN];       // exp(0.2*dst)

// ---------------------------------------------------------------------------
// Arch-agnostic tensor-core helpers (generic PTX, works on compute_103)
// ---------------------------------------------------------------------------
__device__ __forceinline__ uint32_t smem_u32(const void* p) {
    uint32_t a;
    asm("{ .reg .u64 t; cvta.to.shared.u64 t, %1; cvt.u32.u64 %0, t; }" : "=r"(a) : "l"(p));
    return a;
}
__device__ __forceinline__ void ldsm_x4(uint32_t* r, uint32_t addr) {
    asm volatile("ldmatrix.sync.aligned.m8n8.x4.shared.b16 {%0,%1,%2,%3}, [%4];"
        : "=r"(r[0]), "=r"(r[1]), "=r"(r[2]), "=r"(r[3]) : "r"(addr));
}
__device__ __forceinline__ void mma16816(float* c, const uint32_t* a, const uint32_t* b) {
    asm volatile("mma.sync.aligned.m16n8k16.row.col.f32.bf16.bf16.f32 "
        "{%0,%1,%2,%3}, {%4,%5,%6,%7}, {%8,%9}, {%0,%1,%2,%3};"
        : "+f"(c[0]), "+f"(c[1]), "+f"(c[2]), "+f"(c[3])
        : "r"(a[0]), "r"(a[1]), "r"(a[2]), "r"(a[3]), "r"(b[0]), "r"(b[1]));
}

// ---------------------------------------------------------------------------
// Kernel 1 (fused): h_prime = h @ w  ->  bf16 transposed copy (MMA B operand)
//                   + tanh / a_src / a_dst dots + factorized exponentials
//                   + adjacency bitmask pack (MLP-8 ballot batches).
// grid (N/64, KH), 256 threads.
// ---------------------------------------------------------------------------
__global__ void k_hproj(const float* __restrict__ h, const float* __restrict__ w,
                        const float* __restrict__ a_src, const float* __restrict__ a_dst,
                        const float* __restrict__ adj) {
    const int kh = blockIdx.y;
    const int n0 = blockIdx.x * 64;
    __shared__ float shT[64][68];     // [d][i]  (transposed h tile)
    __shared__ float buf[64 * 68];    // first 4096 floats: w tile; reused as [o][n] (stride 68)
    __shared__ float sa[128];         // a_src[kh][o], a_dst[kh][o]
    const int tid = threadIdx.x;

    if (tid < 64) {
        sa[tid]      = a_src[kh * 64 + tid];
        sa[64 + tid] = a_dst[kh * 64 + tid];
    }

    const float4* wkh = (const float4*)(w + (size_t)kh * 64 * 64);
    #pragma unroll
    for (int it = 0; it < 4; it++) ((float4*)buf)[tid + it * 256] = wkh[tid + it * 256];

    {
        const int d = tid & 63, ig0 = tid >> 6;
        #pragma unroll
        for (int it = 0; it < 4; it++) {
            const int ig = ig0 + it * 4;
            float4 v;
            v.x = h[(size_t)(n0 + ig * 4 + 0) * DD + d];
            v.y = h[(size_t)(n0 + ig * 4 + 1) * DD + d];
            v.z = h[(size_t)(n0 + ig * 4 + 2) * DD + d];
            v.w = h[(size_t)(n0 + ig * 4 + 3) * DD + d];
            *(float4*)&shT[d][ig * 4] = v;
        }
    }
    __syncthreads();

    const int ty = tid >> 4, tx = tid & 15;
    float acc[4][4] = {};
    #pragma unroll 8
    for (int j = 0; j < 64; j++) {
        const float4 pv = *(const float4*)&shT[j][ty * 4];
        const float4 hv = *(const float4*)&buf[j * 64 + tx * 4];
        acc[0][0] += pv.x * hv.x; acc[0][1] += pv.x * hv.y; acc[0][2] += pv.x * hv.z; acc[0][3] += pv.x * hv.w;
        acc[1][0] += pv.y * hv.x; acc[1][1] += pv.y * hv.y; acc[1][2] += pv.y * hv.z; acc[1][3] += pv.y * hv.w;
        acc[2][0] += pv.z * hv.x; acc[2][1] += pv.z * hv.y; acc[2][2] += pv.z * hv.z; acc[2][3] += pv.z * hv.w;
        acc[3][0] += pv.w * hv.x; acc[3][1] += pv.w * hv.y; acc[3][2] += pv.w * hv.z; acc[3][3] += pv.w * hv.w;
    }

    // ---- fused attvec: per-row tanh-dot partials, reduce across tx ----
    {
        float pas[4] = {}, pad[4] = {};
        #pragma unroll
        for (int r = 0; r < 4; r++)
            #pragma unroll
            for (int c = 0; c < 4; c++) {
                const float t = tanhf(acc[r][c]);
                pas[r] += t * sa[tx * 4 + c];
                pad[r] += t * sa[64 + tx * 4 + c];
            }
        #pragma unroll
        for (int off = 1; off < 16; off <<= 1)
            #pragma unroll
            for (int r = 0; r < 4; r++) {
                pas[r] += __shfl_xor_sync(0xFFFFFFFFu, pas[r], off);
                pad[r] += __shfl_xor_sync(0xFFFFFFFFu, pad[r], off);
            }
        if (tx == 0) {
            #pragma unroll
            for (int r = 0; r < 4; r++) {
                const int idx = kh * NN + n0 + ty * 4 + r;
                const float as = pas[r], ad = pad[r];
                g_thr [idx] = -as;
                g_es1 [idx] = expf(as);
                g_es2 [idx] = expf(0.2f * as);
                g_dstv[idx] = ad;
                g_ed1 [idx] = expf(ad);
                g_ed2 [idx] = expf(0.2f * ad);
            }
        }
    }

    __syncthreads();            // done reading buf as w-tile
    // transpose into buf as [o][n_local], stride 68 to avoid conflicts
    #pragma unroll
    for (int r = 0; r < 4; r++)
        #pragma unroll
        for (int c = 0; c < 4; c++)
            buf[(tx * 4 + c) * 68 + ty * 4 + r] = acc[r][c];
    __syncthreads();
    // write bf16 transposed rows: thread -> row o = tid>>2, 16 n values
    {
        const int o = tid >> 2, nc = (tid & 3) * 16;
        __nv_bfloat162 tmp[8];
        #pragma unroll
        for (int j = 0; j < 8; j++)
            tmp[j] = __floats2bfloat162_rn(buf[o * 68 + nc + 2 * j], buf[o * 68 + nc + 2 * j + 1]);
        __nv_bfloat16* dst = g_hpT + ((size_t)kh * 64 + o) * NN + n0 + nc;
        *(uint4*)dst       = ((uint4*)tmp)[0];
        *(uint4*)(dst + 8) = ((uint4*)tmp)[1];
    }

    // ---- adjacency bitmask pack: 8 words per warp iteration (MLP=8) ----
    {
        const int lane = tid & 31;
        const int gwarp = ((blockIdx.y * gridDim.x + blockIdx.x) * 256 + tid) >> 5;  // 0..4095
        const int nwarps = (gridDim.x * gridDim.y * 256) >> 5;                       // 4096
        // each warp owns words [gwarp*8, ...) stepping nwarps*8; 32 iterations
        for (int wd = gwarp * 8; wd < TOTAL_WORDS; wd += nwarps * 8) {
            float v0 = adj[(size_t)(wd + 0) * 32 + lane];
            float v1 = adj[(size_t)(wd + 1) * 32 + lane];
            float v2 = adj[(size_t)(wd + 2) * 32 + lane];
            float v3 = adj[(size_t)(wd + 3) * 32 + lane];
            float v4 = adj[(size_t)(wd + 4) * 32 + lane];
            float v5 = adj[(size_t)(wd + 5) * 32 + lane];
            float v6 = adj[(size_t)(wd + 6) * 32 + lane];
            float v7 = adj[(size_t)(wd + 7) * 32 + lane];
            uint32_t b0 = __ballot_sync(0xFFFFFFFFu, v0 != 0.0f);
            uint32_t b1 = __ballot_sync(0xFFFFFFFFu, v1 != 0.0f);
            uint32_t b2 = __ballot_sync(0xFFFFFFFFu, v2 != 0.0f);
            uint32_t b3 = __ballot_sync(0xFFFFFFFFu, v3 != 0.0f);
            uint32_t b4 = __ballot_sync(0xFFFFFFFFu, v4 != 0.0f);
            uint32_t b5 = __ballot_sync(0xFFFFFFFFu, v5 != 0.0f);
            uint32_t b6 = __ballot_sync(0xFFFFFFFFu, v6 != 0.0f);
            uint32_t b7 = __ballot_sync(0xFFFFFFFFu, v7 != 0.0f);
            if (lane == 0) {
                uint4 w0 = make_uint4(b0, b1, b2, b3);
                uint4 w1 = make_uint4(b4, b5, b6, b7);
                *(uint4*)(g_mask + wd)     = w0;
                *(uint4*)(g_mask + wd + 4) = w1;
            }
        }
    }
}

// ---------------------------------------------------------------------------
// Kernel 2 (dominant, mma.sync bf16): ONE head per CTA, bitmask adjacency
// (L2-resident), DOUBLE-BUFFERED P/B smem (1 sync per chunk), prefetch
// issued BEFORE the barrier so LDG latency hides under sync-wait + mma.
//   D[128,64] += P[128,64]_bf16 @ HpT[64(o),64(m)]_bf16^T   (chunks over m)
//   P[n,m] = bit(k,n,m) * (dst[m] >= -src[n] ? es1[n]*ed1[m] : es2[n]*ed2[m])
// grid (N/128=32, K=2, H=4), 256 threads (8 warps), dynamic smem 58KB.
// Row consts packed (thr,e1,e2,pad) float4 -> 1 LDS.128 per row-group.
// ---------------------------------------------------------------------------
#define P_OFF   0
#define PH_B    18432
#define B_OFF   36864
#define BH_B    9216
#define RC_OFF  55296     // 128 rows x float4 = 2048 B
#define D_OFF   57344     // 512 B
#define SMEM_DYN 57856

__global__ void __launch_bounds__(256, 2) k_main9() {
    extern __shared__ char sm[];
    const uint32_t smb = smem_u32(sm);
    const int tid  = threadIdx.x;
    const int wid  = tid >> 5;
    const int lane = tid & 31;
    const int k    = blockIdx.y;
    const int hh   = blockIdx.z;
    const int n0   = blockIdx.x * 128;
    const int kh   = k * HH + hh;

    // stage packed row-side constants into smem: [row] = (thr, e1, e2, 0)
    if (tid < 128) {
        const int ridx = kh * NN + n0 + tid;
        float4 rc;
        rc.x = g_thr[ridx];
        rc.y = g_es1[ridx];
        rc.z = g_es2[ridx];
        rc.w = 0.0f;
        ((float4*)(sm + RC_OFF))[tid] = rc;
    }

    // P-build mapping: fixed cols, walk rows
    const int g     = tid >> 4;          // 0..15
    const int cbase = (tid & 15) * 4;    // 0..60
    const int wsel  = cbase >> 5;
    const int shift = cbase & 31;
    const uint32_t* mrow = g_mask + (size_t)k * NN * NW32 + (size_t)(n0 + g) * NW32 + wsel;
    const float* mdv = g_dstv + kh * NN;
    const float* me1 = g_ed1  + kh * NN;
    const float* me2 = g_ed2  + kh * NN;

    // B tile load mapping: 64 rows x 64 bf16 = 512 uint4, 2 per thread
    const int brow0 = tid >> 3,          bcol0 = tid & 7;
    const int brow1 = (tid + 256) >> 3,  bcol1 = tid & 7;
    const __nv_bfloat16* hptk = g_hpT + (size_t)kh * 64 * NN;

    // mma warp mapping: warp -> (row slab = wid&3, o-half = wid>>2)
    const int slab  = wid & 3;
    const int ohalf = wid >> 2;
    const int mbase = slab * 32;
    const int a_row = ((lane >> 3) & 1) * 8 + (lane & 7);
    const int a_k   = (lane >> 4) * 8;
    const uint32_t aAddr = smb + P_OFF + (mbase + a_row) * 144 + a_k * 2;
    const int b_n = ((lane >> 4) & 1) * 8 + (lane & 7);
    const int b_k = ((lane >> 3) & 1) * 8;
    const uint32_t bAddr = smb + B_OFF + (ohalf * 32 + b_n) * 144 + b_k * 2;

    float acc[2][4][4];     // [row 16-slab][o-frag][c]
    #pragma unroll
    for (int a = 0; a < 2; a++)
        #pragma unroll
        for (int b = 0; b < 4; b++)
            #pragma unroll
            for (int cc = 0; cc < 4; cc++) acc[a][b][cc] = 0.0f;
    float den[8];
    #pragma unroll
    for (int j = 0; j < 8; j++) den[j] = 0.0f;

    const float4* srcv = (const float4*)(sm + RC_OFF);

    // ---- prefetch chunk 0 ----
    uint32_t mw[8];
    uint4  bq0, bq1;
    float4 dv4, q14, q24;
    {
        #pragma unroll
        for (int j = 0; j < 8; j++)
            mw[j] = mrow[(size_t)(j * 16) * NW32];
        bq0 = *(const uint4*)(hptk + (size_t)brow0 * NN + bcol0 * 8);
        bq1 = *(const uint4*)(hptk + (size_t)brow1 * NN + bcol1 * 8);
        dv4 = *(const float4*)(mdv + cbase);
        q14 = *(const float4*)(me1 + cbase);
        q24 = *(const float4*)(me2 + cbase);
    }
    __syncthreads();   // row consts visible

    for (int c = 0; c < NN / 64; c++) {
        const int buf = c & 1;

        // ---- stage B (from prefetched regs) ----
        *(uint4*)(sm + B_OFF + buf * BH_B + brow0 * 144 + bcol0 * 16) = bq0;
        *(uint4*)(sm + B_OFF + buf * BH_B + brow1 * 144 + bcol1 * 16) = bq1;

        // ---- build P tile (bf16): 8 rows x 4 cols per thread ----
        #pragma unroll
        for (int j = 0; j < 8; j++) {
            const int row = g + j * 16;
            const float4 rc = srcv[row];     // (thr, e1, e2, -)
            const uint32_t bits = mw[j] >> shift;
            const float v0 = (dv4.x >= rc.x) ? rc.y * q14.x : rc.z * q24.x;
            const float v1 = (dv4.y >= rc.x) ? rc.y * q14.y : rc.z * q24.y;
            const float v2 = (dv4.z >= rc.x) ? rc.y * q14.z : rc.z * q24.z;
            const float v3 = (dv4.w >= rc.x) ? rc.y * q14.w : rc.z * q24.w;
            const float p0 = (bits & 1u) ? v0 : 0.0f;
            const float p1 = (bits & 2u) ? v1 : 0.0f;
            const float p2 = (bits & 4u) ? v2 : 0.0f;
            const float p3 = (bits & 8u) ? v3 : 0.0f;
            den[j] += (p0 + p1) + (p2 + p3);
            __nv_bfloat162 lo = __floats2bfloat162_rn(p0, p1);
            __nv_bfloat162 hi = __floats2bfloat162_rn(p2, p3);
            uint2 v;
            v.x = *(uint32_t*)&lo;
            v.y = *(uint32_t*)&hi;
            *(uint2*)(sm + P_OFF + buf * PH_B + row * 144 + cbase * 2) = v;
        }

        // ---- prefetch chunk c+1 BEFORE the barrier (flies under sync+mma) ----
        if (c < NN / 64 - 1) {
            const int mt = (c + 1) << 6;
            #pragma unroll
            for (int j = 0; j < 8; j++)
                mw[j] = mrow[(size_t)(j * 16) * NW32 + (mt >> 5)];
            bq0 = *(const uint4*)(hptk + (size_t)brow0 * NN + mt + bcol0 * 8);
            bq1 = *(const uint4*)(hptk + (size_t)brow1 * NN + mt + bcol1 * 8);
            dv4 = *(const float4*)(mdv + mt + cbase);
            q14 = *(const float4*)(me1 + mt + cbase);
            q24 = *(const float4*)(me2 + mt + cbase);
        }

        __syncthreads();   // this chunk's P + B visible; prior chunk's mma reads done

        // ---- tensor cores: 32 x m16n8k16 per warp ----
        const uint32_t aB = aAddr + buf * PH_B;
        const uint32_t bB = bAddr + buf * BH_B;
        #pragma unroll
        for (int ks = 0; ks < 4; ks++) {
            uint32_t af0[4], af1[4];
            ldsm_x4(af0, aB + ks * 32);
            ldsm_x4(af1, aB + 16 * 144 + ks * 32);
            #pragma unroll
            for (int nt = 0; nt < 2; nt++) {
                uint32_t bf[4];
                ldsm_x4(bf, bB + nt * (16 * 144) + ks * 32);
                mma16816(acc[0][2 * nt],     af0, bf);
                mma16816(acc[0][2 * nt + 1], af0, bf + 2);
                mma16816(acc[1][2 * nt],     af1, bf);
                mma16816(acc[1][2 * nt + 1], af1, bf + 2);
            }
        }
    }

    // ---- denominator reduce: 16 col-owner lanes per row ----
    #pragma unroll
    for (int j = 0; j < 8; j++) {
        float v = den[j];
        v += __shfl_xor_sync(0xFFFFFFFFu, v, 8);
        v += __shfl_xor_sync(0xFFFFFFFFu, v, 4);
        v += __shfl_xor_sync(0xFFFFFFFFu, v, 2);
        v += __shfl_xor_sync(0xFFFFFFFFu, v, 1);
        if ((tid & 15) == 0)
            ((float*)(sm + D_OFF))[g + j * 16] = v;
    }
    __syncthreads();

    // ---- epilogue: scale by 1/den, store ----
    const float* sden = (const float*)(sm + D_OFF);
    #pragma unroll
    for (int mt2 = 0; mt2 < 2; mt2++) {
        const int row0 = mbase + mt2 * 16 + (lane >> 2);
        const float inv0 = 1.0f / sden[row0];
        const float inv1 = 1.0f / sden[row0 + 8];
        float* op0 = g_att + ((size_t)kh * NN + n0 + row0) * OO;
        float* op1 = op0 + 8 * OO;
        #pragma unroll
        for (int j = 0; j < 4; j++) {
            const int col = ohalf * 32 + j * 8 + (lane & 3) * 2;
            float2 v0 = make_float2(acc[mt2][j][0] * inv0, acc[mt2][j][1] * inv0);
            float2 v1 = make_float2(acc[mt2][j][2] * inv1, acc[mt2][j][3] * inv1);
            *(float2*)(op0 + col) = v0;
            *(float2*)(op1 + col) = v1;
        }
    }
}

// ---------------------------------------------------------------------------
// Kernel 3: head-mean -> concat -> fc (C=2) -> log_softmax.
// ---------------------------------------------------------------------------
__global__ void k_final(const float* __restrict__ fc_w, const float* __restrict__ fc_b,
                        float* __restrict__ out) {
    const int wg = blockIdx.x * 8 + (threadIdx.x >> 5);
    if (wg >= NUSER) return;
    const int lane = threadIdx.x & 31;
    const int n = wg;

    float l0 = 0.0f, l1 = 0.0f;
    #pragma unroll
    for (int u = 0; u < 4; u++) {
        const int d = lane + u * 32;
        const int k = d >> 6, o = d & 63;
        float e = 0.0f;
        #pragma unroll
        for (int h = 0; h < HH; h++)
            e += g_att[(((size_t)(k * HH + h) * NN) + n) * OO + o];
        e *= 0.25f;
        l0 += e * fc_w[d];
        l1 += e * fc_w[128 + d];
    }
    #pragma unroll
    for (int off = 16; off; off >>= 1) {
        l0 += __shfl_xor_sync(0xFFFFFFFFu, l0, off);
        l1 += __shfl_xor_sync(0xFFFFFFFFu, l1, off);
    }
    if (lane == 0) {
        l0 += fc_b[0];
        l1 += fc_b[1];
        const float mx  = fmaxf(l0, l1);
        const float lse = mx + logf(expf(l0 - mx) + expf(l1 - mx));
        out[n * 2 + 0] = l0 - lse;
        out[n * 2 + 1] = l1 - lse;
    }
}

// ---------------------------------------------------------------------------
extern "C" void kernel_launch(void* const* d_in, const int* in_sizes, int n_in,
                              void* d_out, int out_size) {
    (void)in_sizes; (void)n_in; (void)out_size;
    const float* h     = (const float*)d_in[0];
    const float* hadj  = (const float*)d_in[1];
    const float* w     = (const float*)d_in[2];
    const float* a_src = (const float*)d_in[3];
    const float* a_dst = (const float*)d_in[4];
    const float* fc_w  = (const float*)d_in[5];
    const float* fc_b  = (const float*)d_in[6];
    float* out = (float*)d_out;

    static int smem_set = 0;
    if (!smem_set) {
        cudaFuncSetAttribute(k_main9, cudaFuncAttributeMaxDynamicSharedMemorySize, SMEM_DYN);
        smem_set = 1;
    }

    k_hproj <<<dim3(NN / 64, KHT), 256>>>(h, w, a_src, a_dst, hadj);
    k_main9 <<<dim3(NN / 128, KK, HH), 256, SMEM_DYN>>>();
    k_final <<<NUSER / 8, 256>>>(fc_w, fc_b, out);
}

// round 14
// speedup vs baseline: 1.3654x; 1.0076x over previous
#include <cuda_runtime.h>
#include <cuda_bf16.h>
#include <math.h>
#include <stdint.h>

// Problem constants
#define NN    4096
#define DD    64
#define HH    4
#define OO    64
#define KK    2
#define KHT   8        // K*H
#define NUSER 4000
#define CC    2
#define NW32  (NN / 32)                 // mask words per row = 128
#define TOTAL_WORDS (KK * NN * NW32)    // 1,048,576

// Device scratch (allocation-free rule: static __device__ arrays)
__device__ __nv_bfloat16 g_hpT[KHT * OO * NN];   // h_prime transposed [kh][o][m] bf16 (4 MB)
__device__ float         g_att[KHT * NN * OO];   // attention output per (k,h)  (8 MB)
__device__ uint32_t      g_mask[TOTAL_WORDS];    // adjacency bitmask (4 MB)
__device__ float g_thr [KHT * NN];       // -src[n]
__device__ float g_es1 [KHT * NN];       // exp(src)
__device__ float g_es2 [KHT * NN];       // exp(0.2*src)
__device__ float g_dstv[KHT * NN];       // dst[m]
__device__ float g_ed1 [KHT * NN];       // exp(dst)
__device__ float g_ed2 [KHT * NN];       // exp(0.2*dst)

// ---------------------------------------------------------------------------
// Arch-agnostic tensor-core helpers (generic PTX, works on compute_103)
// ---------------------------------------------------------------------------
__device__ __forceinline__ uint32_t smem_u32(const void* p) {
    uint32_t a;
    asm("{ .reg .u64 t; cvta.to.shared.u64 t, %1; cvt.u32.u64 %0, t; }" : "=r"(a) : "l"(p));
    return a;
}
__device__ __forceinline__ void ldsm_x4(uint32_t* r, uint32_t addr) {
    asm volatile("ldmatrix.sync.aligned.m8n8.x4.shared.b16 {%0,%1,%2,%3}, [%4];"
        : "=r"(r[0]), "=r"(r[1]), "=r"(r[2]), "=r"(r[3]) : "r"(addr));
}
__device__ __forceinline__ void mma16816(float* c, const uint32_t* a, const uint32_t* b) {
    asm volatile("mma.sync.aligned.m16n8k16.row.col.f32.bf16.bf16.f32 "
        "{%0,%1,%2,%3}, {%4,%5,%6,%7}, {%8,%9}, {%0,%1,%2,%3};"
        : "+f"(c[0]), "+f"(c[1]), "+f"(c[2]), "+f"(c[3])
        : "r"(a[0]), "r"(a[1]), "r"(a[2]), "r"(a[3]), "r"(b[0]), "r"(b[1]));
}

// ---------------------------------------------------------------------------
// Kernel 0 (stream 2, overlaps k_hproj): pack adjacency into bitmask.
// MLP-8 ballot batches; grid 2048 -> 16384 warps, 8 iterations each.
// ---------------------------------------------------------------------------
__global__ void k_pack(const float* __restrict__ adj) {
    const int tid  = threadIdx.x;
    const int lane = tid & 31;
    const int gwarp  = ((blockIdx.x << 8) + tid) >> 5;
    const int nwarps = (gridDim.x << 8) >> 5;
    for (int wd = gwarp * 8; wd < TOTAL_WORDS; wd += nwarps * 8) {
        float v0 = adj[(size_t)(wd + 0) * 32 + lane];
        float v1 = adj[(size_t)(wd + 1) * 32 + lane];
        float v2 = adj[(size_t)(wd + 2) * 32 + lane];
        float v3 = adj[(size_t)(wd + 3) * 32 + lane];
        float v4 = adj[(size_t)(wd + 4) * 32 + lane];
        float v5 = adj[(size_t)(wd + 5) * 32 + lane];
        float v6 = adj[(size_t)(wd + 6) * 32 + lane];
        float v7 = adj[(size_t)(wd + 7) * 32 + lane];
        uint32_t b0 = __ballot_sync(0xFFFFFFFFu, v0 != 0.0f);
        uint32_t b1 = __ballot_sync(0xFFFFFFFFu, v1 != 0.0f);
        uint32_t b2 = __ballot_sync(0xFFFFFFFFu, v2 != 0.0f);
        uint32_t b3 = __ballot_sync(0xFFFFFFFFu, v3 != 0.0f);
        uint32_t b4 = __ballot_sync(0xFFFFFFFFu, v4 != 0.0f);
        uint32_t b5 = __ballot_sync(0xFFFFFFFFu, v5 != 0.0f);
        uint32_t b6 = __ballot_sync(0xFFFFFFFFu, v6 != 0.0f);
        uint32_t b7 = __ballot_sync(0xFFFFFFFFu, v7 != 0.0f);
        if (lane == 0) {
            *(uint4*)(g_mask + wd)     = make_uint4(b0, b1, b2, b3);
            *(uint4*)(g_mask + wd + 4) = make_uint4(b4, b5, b6, b7);
        }
    }
}

// ---------------------------------------------------------------------------
// Kernel 1 (fused): h_prime = h @ w  ->  bf16 transposed copy (MMA B operand)
//                   + tanh / a_src / a_dst dots + factorized exponentials.
// grid (N/64, KH), 256 threads.
// ---------------------------------------------------------------------------
__global__ void k_hproj(const float* __restrict__ h, const float* __restrict__ w,
                        const float* __restrict__ a_src, const float* __restrict__ a_dst) {
    const int kh = blockIdx.y;
    const int n0 = blockIdx.x * 64;
    __shared__ float shT[64][68];     // [d][i]  (transposed h tile)
    __shared__ float buf[64 * 68];    // first 4096 floats: w tile; reused as [o][n] (stride 68)
    __shared__ float sa[128];         // a_src[kh][o], a_dst[kh][o]
    const int tid = threadIdx.x;

    if (tid < 64) {
        sa[tid]      = a_src[kh * 64 + tid];
        sa[64 + tid] = a_dst[kh * 64 + tid];
    }

    const float4* wkh = (const float4*)(w + (size_t)kh * 64 * 64);
    #pragma unroll
    for (int it = 0; it < 4; it++) ((float4*)buf)[tid + it * 256] = wkh[tid + it * 256];

    {
        const int d = tid & 63, ig0 = tid >> 6;
        #pragma unroll
        for (int it = 0; it < 4; it++) {
            const int ig = ig0 + it * 4;
            float4 v;
            v.x = h[(size_t)(n0 + ig * 4 + 0) * DD + d];
            v.y = h[(size_t)(n0 + ig * 4 + 1) * DD + d];
            v.z = h[(size_t)(n0 + ig * 4 + 2) * DD + d];
            v.w = h[(size_t)(n0 + ig * 4 + 3) * DD + d];
            *(float4*)&shT[d][ig * 4] = v;
        }
    }
    __syncthreads();

    const int ty = tid >> 4, tx = tid & 15;
    float acc[4][4] = {};
    #pragma unroll 8
    for (int j = 0; j < 64; j++) {
        const float4 pv = *(const float4*)&shT[j][ty * 4];
        const float4 hv = *(const float4*)&buf[j * 64 + tx * 4];
        acc[0][0] += pv.x * hv.x; acc[0][1] += pv.x * hv.y; acc[0][2] += pv.x * hv.z; acc[0][3] += pv.x * hv.w;
        acc[1][0] += pv.y * hv.x; acc[1][1] += pv.y * hv.y; acc[1][2] += pv.y * hv.z; acc[1][3] += pv.y * hv.w;
        acc[2][0] += pv.z * hv.x; acc[2][1] += pv.z * hv.y; acc[2][2] += pv.z * hv.z; acc[2][3] += pv.z * hv.w;
        acc[3][0] += pv.w * hv.x; acc[3][1] += pv.w * hv.y; acc[3][2] += pv.w * hv.z; acc[3][3] += pv.w * hv.w;
    }

    // ---- fused attvec: per-row tanh-dot partials, reduce across tx ----
    {
        float pas[4] = {}, pad[4] = {};
        #pragma unroll
        for (int r = 0; r < 4; r++)
            #pragma unroll
            for (int c = 0; c < 4; c++) {
                const float t = tanhf(acc[r][c]);
                pas[r] += t * sa[tx * 4 + c];
                pad[r] += t * sa[64 + tx * 4 + c];
            }
        #pragma unroll
        for (int off = 1; off < 16; off <<= 1)
            #pragma unroll
            for (int r = 0; r < 4; r++) {
                pas[r] += __shfl_xor_sync(0xFFFFFFFFu, pas[r], off);
                pad[r] += __shfl_xor_sync(0xFFFFFFFFu, pad[r], off);
            }
        if (tx == 0) {
            #pragma unroll
            for (int r = 0; r < 4; r++) {
                const int idx = kh * NN + n0 + ty * 4 + r;
                const float as = pas[r], ad = pad[r];
                g_thr [idx] = -as;
                g_es1 [idx] = expf(as);
                g_es2 [idx] = expf(0.2f * as);
                g_dstv[idx] = ad;
                g_ed1 [idx] = expf(ad);
                g_ed2 [idx] = expf(0.2f * ad);
            }
        }
    }

    __syncthreads();            // done reading buf as w-tile
    // transpose into buf as [o][n_local], stride 68 to avoid conflicts
    #pragma unroll
    for (int r = 0; r < 4; r++)
        #pragma unroll
        for (int c = 0; c < 4; c++)
            buf[(tx * 4 + c) * 68 + ty * 4 + r] = acc[r][c];
    __syncthreads();
    // write bf16 transposed rows: thread -> row o = tid>>2, 16 n values
    {
        const int o = tid >> 2, nc = (tid & 3) * 16;
        __nv_bfloat162 tmp[8];
        #pragma unroll
        for (int j = 0; j < 8; j++)
            tmp[j] = __floats2bfloat162_rn(buf[o * 68 + nc + 2 * j], buf[o * 68 + nc + 2 * j + 1]);
        __nv_bfloat16* dst = g_hpT + ((size_t)kh * 64 + o) * NN + n0 + nc;
        *(uint4*)dst       = ((uint4*)tmp)[0];
        *(uint4*)(dst + 8) = ((uint4*)tmp)[1];
    }
}

// ---------------------------------------------------------------------------
// Kernel 2 (dominant, mma.sync bf16): ONE head per CTA, bitmask adjacency
// (L2-resident), DOUBLE-BUFFERED P/B smem (1 sync per chunk), prefetch
// issued BEFORE the barrier so LDG latency hides under sync-wait + mma.
//   D[128,64] += P[128,64]_bf16 @ HpT[64(o),64(m)]_bf16^T   (chunks over m)
//   P[n,m] = bit(k,n,m) * (dst[m] >= -src[n] ? es1[n]*ed1[m] : es2[n]*ed2[m])
// grid (N/128=32, K=2, H=4), 256 threads (8 warps), dynamic smem 58KB.
// ---------------------------------------------------------------------------
#define P_OFF   0
#define PH_B    18432
#define B_OFF   36864
#define BH_B    9216
#define RC_OFF  55296     // 128 rows x float4 = 2048 B
#define D_OFF   57344     // 512 B
#define SMEM_DYN 57856

__global__ void __launch_bounds__(256, 2) k_main9() {
    extern __shared__ char sm[];
    const uint32_t smb = smem_u32(sm);
    const int tid  = threadIdx.x;
    const int wid  = tid >> 5;
    const int lane = tid & 31;
    const int k    = blockIdx.y;
    const int hh   = blockIdx.z;
    const int n0   = blockIdx.x * 128;
    const int kh   = k * HH + hh;

    // stage packed row-side constants into smem: [row] = (thr, e1, e2, 0)
    if (tid < 128) {
        const int ridx = kh * NN + n0 + tid;
        float4 rc;
        rc.x = g_thr[ridx];
        rc.y = g_es1[ridx];
        rc.z = g_es2[ridx];
        rc.w = 0.0f;
        ((float4*)(sm + RC_OFF))[tid] = rc;
    }

    // P-build mapping: fixed cols, walk rows
    const int g     = tid >> 4;          // 0..15
    const int cbase = (tid & 15) * 4;    // 0..60
    const int wsel  = cbase >> 5;
    const int shift = cbase & 31;
    const uint32_t* mrow = g_mask + (size_t)k * NN * NW32 + (size_t)(n0 + g) * NW32 + wsel;
    const float* mdv = g_dstv + kh * NN;
    const float* me1 = g_ed1  + kh * NN;
    const float* me2 = g_ed2  + kh * NN;

    // B tile load mapping: 64 rows x 64 bf16 = 512 uint4, 2 per thread
    const int brow0 = tid >> 3,          bcol0 = tid & 7;
    const int brow1 = (tid + 256) >> 3,  bcol1 = tid & 7;
    const __nv_bfloat16* hptk = g_hpT + (size_t)kh * 64 * NN;

    // mma warp mapping: warp -> (row slab = wid&3, o-half = wid>>2)
    const int slab  = wid & 3;
    const int ohalf = wid >> 2;
    const int mbase = slab * 32;
    const int a_row = ((lane >> 3) & 1) * 8 + (lane & 7);
    const int a_k   = (lane >> 4) * 8;
    const uint32_t aAddr = smb + P_OFF + (mbase + a_row) * 144 + a_k * 2;
    const int b_n = ((lane >> 4) & 1) * 8 + (lane & 7);
    const int b_k = ((lane >> 3) & 1) * 8;
    const uint32_t bAddr = smb + B_OFF + (ohalf * 32 + b_n) * 144 + b_k * 2;

    float acc[2][4][4];     // [row 16-slab][o-frag][c]
    #pragma unroll
    for (int a = 0; a < 2; a++)
        #pragma unroll
        for (int b = 0; b < 4; b++)
            #pragma unroll
            for (int cc = 0; cc < 4; cc++) acc[a][b][cc] = 0.0f;
    float den[8];
    #pragma unroll
    for (int j = 0; j < 8; j++) den[j] = 0.0f;

    const float4* srcv = (const float4*)(sm + RC_OFF);

    // ---- prefetch chunk 0 ----
    uint32_t mw[8];
    uint4  bq0, bq1;
    float4 dv4, q14, q24;
    {
        #pragma unroll
        for (int j = 0; j < 8; j++)
            mw[j] = mrow[(size_t)(j * 16) * NW32];
        bq0 = *(const uint4*)(hptk + (size_t)brow0 * NN + bcol0 * 8);
        bq1 = *(const uint4*)(hptk + (size_t)brow1 * NN + bcol1 * 8);
        dv4 = *(const float4*)(mdv + cbase);
        q14 = *(const float4*)(me1 + cbase);
        q24 = *(const float4*)(me2 + cbase);
    }
    __syncthreads();   // row consts visible

    for (int c = 0; c < NN / 64; c++) {
        const int buf = c & 1;

        // ---- stage B (from prefetched regs) ----
        *(uint4*)(sm + B_OFF + buf * BH_B + brow0 * 144 + bcol0 * 16) = bq0;
        *(uint4*)(sm + B_OFF + buf * BH_B + brow1 * 144 + bcol1 * 16) = bq1;

        // ---- build P tile (bf16): 8 rows x 4 cols per thread ----
        #pragma unroll
        for (int j = 0; j < 8; j++) {
            const int row = g + j * 16;
            const float4 rc = srcv[row];     // (thr, e1, e2, -)
            const uint32_t bits = mw[j] >> shift;
            const float v0 = (dv4.x >= rc.x) ? rc.y * q14.x : rc.z * q24.x;
            const float v1 = (dv4.y >= rc.x) ? rc.y * q14.y : rc.z * q24.y;
            const float v2 = (dv4.z >= rc.x) ? rc.y * q14.z : rc.z * q24.z;
            const float v3 = (dv4.w >= rc.x) ? rc.y * q14.w : rc.z * q24.w;
            const float p0 = (bits & 1u) ? v0 : 0.0f;
            const float p1 = (bits & 2u) ? v1 : 0.0f;
            const float p2 = (bits & 4u) ? v2 : 0.0f;
            const float p3 = (bits & 8u) ? v3 : 0.0f;
            den[j] += (p0 + p1) + (p2 + p3);
            __nv_bfloat162 lo = __floats2bfloat162_rn(p0, p1);
            __nv_bfloat162 hi = __floats2bfloat162_rn(p2, p3);
            uint2 v;
            v.x = *(uint32_t*)&lo;
            v.y = *(uint32_t*)&hi;
            *(uint2*)(sm + P_OFF + buf * PH_B + row * 144 + cbase * 2) = v;
        }

        // ---- prefetch chunk c+1 BEFORE the barrier (flies under sync+mma) ----
        if (c < NN / 64 - 1) {
            const int mt = (c + 1) << 6;
            #pragma unroll
            for (int j = 0; j < 8; j++)
                mw[j] = mrow[(size_t)(j * 16) * NW32 + (mt >> 5)];
            bq0 = *(const uint4*)(hptk + (size_t)brow0 * NN + mt + bcol0 * 8);
            bq1 = *(const uint4*)(hptk + (size_t)brow1 * NN + mt + bcol1 * 8);
            dv4 = *(const float4*)(mdv + mt + cbase);
            q14 = *(const float4*)(me1 + mt + cbase);
            q24 = *(const float4*)(me2 + mt + cbase);
        }

        __syncthreads();   // this chunk's P + B visible; prior chunk's mma reads done

        // ---- tensor cores: 32 x m16n8k16 per warp ----
        const uint32_t aB = aAddr + buf * PH_B;
        const uint32_t bB = bAddr + buf * BH_B;
        #pragma unroll
        for (int ks = 0; ks < 4; ks++) {
            uint32_t af0[4], af1[4];
            ldsm_x4(af0, aB + ks * 32);
            ldsm_x4(af1, aB + 16 * 144 + ks * 32);
            #pragma unroll
            for (int nt = 0; nt < 2; nt++) {
                uint32_t bf[4];
                ldsm_x4(bf, bB + nt * (16 * 144) + ks * 32);
                mma16816(acc[0][2 * nt],     af0, bf);
                mma16816(acc[0][2 * nt + 1], af0, bf + 2);
                mma16816(acc[1][2 * nt],     af1, bf);
                mma16816(acc[1][2 * nt + 1], af1, bf + 2);
            }
        }
    }

    // ---- denominator reduce: 16 col-owner lanes per row ----
    #pragma unroll
    for (int j = 0; j < 8; j++) {
        float v = den[j];
        v += __shfl_xor_sync(0xFFFFFFFFu, v, 8);
        v += __shfl_xor_sync(0xFFFFFFFFu, v, 4);
        v += __shfl_xor_sync(0xFFFFFFFFu, v, 2);
        v += __shfl_xor_sync(0xFFFFFFFFu, v, 1);
        if ((tid & 15) == 0)
            ((float*)(sm + D_OFF))[g + j * 16] = v;
    }
    __syncthreads();

    // ---- epilogue: scale by 1/den, store ----
    const float* sden = (const float*)(sm + D_OFF);
    #pragma unroll
    for (int mt2 = 0; mt2 < 2; mt2++) {
        const int row0 = mbase + mt2 * 16 + (lane >> 2);
        const float inv0 = 1.0f / sden[row0];
        const float inv1 = 1.0f / sden[row0 + 8];
        float* op0 = g_att + ((size_t)kh * NN + n0 + row0) * OO;
        float* op1 = op0 + 8 * OO;
        #pragma unroll
        for (int j = 0; j < 4; j++) {
            const int col = ohalf * 32 + j * 8 + (lane & 3) * 2;
            float2 v0 = make_float2(acc[mt2][j][0] * inv0, acc[mt2][j][1] * inv0);
            float2 v1 = make_float2(acc[mt2][j][2] * inv1, acc[mt2][j][3] * inv1);
            *(float2*)(op0 + col) = v0;
            *(float2*)(op1 + col) = v1;
        }
    }
}

// ---------------------------------------------------------------------------
// Kernel 3: head-mean -> concat -> fc (C=2) -> log_softmax.
// ---------------------------------------------------------------------------
__global__ void k_final(const float* __restrict__ fc_w, const float* __restrict__ fc_b,
                        float* __restrict__ out) {
    const int wg = blockIdx.x * 8 + (threadIdx.x >> 5);
    if (wg >= NUSER) return;
    const int lane = threadIdx.x & 31;
    const int n = wg;

    float l0 = 0.0f, l1 = 0.0f;
    #pragma unroll
    for (int u = 0; u < 4; u++) {
        const int d = lane + u * 32;
        const int k = d >> 6, o = d & 63;
        float e = 0.0f;
        #pragma unroll
        for (int h = 0; h < HH; h++)
            e += g_att[(((size_t)(k * HH + h) * NN) + n) * OO + o];
        e *= 0.25f;
        l0 += e * fc_w[d];
        l1 += e * fc_w[128 + d];
    }
    #pragma unroll
    for (int off = 16; off; off >>= 1) {
        l0 += __shfl_xor_sync(0xFFFFFFFFu, l0, off);
        l1 += __shfl_xor_sync(0xFFFFFFFFu, l1, off);
    }
    if (lane == 0) {
        l0 += fc_b[0];
        l1 += fc_b[1];
        const float mx  = fmaxf(l0, l1);
        const float lse = mx + logf(expf(l0 - mx) + expf(l1 - mx));
        out[n * 2 + 0] = l0 - lse;
        out[n * 2 + 1] = l1 - lse;
    }
}

// ---------------------------------------------------------------------------
extern "C" void kernel_launch(void* const* d_in, const int* in_sizes, int n_in,
                              void* d_out, int out_size) {
    (void)in_sizes; (void)n_in; (void)out_size;
    const float* h     = (const float*)d_in[0];
    const float* hadj  = (const float*)d_in[1];
    const float* w     = (const float*)d_in[2];
    const float* a_src = (const float*)d_in[3];
    const float* a_dst = (const float*)d_in[4];
    const float* fc_w  = (const float*)d_in[5];
    const float* fc_b  = (const float*)d_in[6];
    float* out = (float*)d_out;

    static cudaStream_t s2 = nullptr;
    static cudaEvent_t evFork = nullptr, evJoin = nullptr;
    static int init_done = 0;
    if (!init_done) {
        cudaFuncSetAttribute(k_main9, cudaFuncAttributeMaxDynamicSharedMemorySize, SMEM_DYN);
        cudaStreamCreateWithFlags(&s2, cudaStreamNonBlocking);
        cudaEventCreateWithFlags(&evFork, cudaEventDisableTiming);
        cudaEventCreateWithFlags(&evJoin, cudaEventDisableTiming);
        init_done = 1;
    }

    // fork: pack (DRAM-bound) runs on s2 concurrently with hproj (FMA-bound)
    cudaEventRecord(evFork, 0);
    cudaStreamWaitEvent(s2, evFork, 0);
    k_pack <<<2048, 256, 0, s2>>>(hadj);
    cudaEventRecord(evJoin, s2);

    k_hproj <<<dim3(NN / 64, KHT), 256>>>(h, w, a_src, a_dst);

    // join: k_main needs both hproj outputs and the mask
    cudaStreamWaitEvent(0, evJoin, 0);
    k_main9 <<<dim3(NN / 128, KK, HH), 256, SMEM_DYN>>>();
    k_final <<<NUSER / 8, 256>>>(fc_w, fc_b, out);
}

// round 15
// speedup vs baseline: 1.5097x; 1.1057x over previous
#include <cuda_runtime.h>
#include <cuda_bf16.h>
#include <math.h>
#include <stdint.h>

// Problem constants
#define NN    4096
#define DD    64
#define HH    4
#define OO    64
#define KK    2
#define KHT   8        // K*H
#define NUSER 4000
#define CC    2

// Device scratch (allocation-free rule: static __device__ arrays)
__device__ __nv_bfloat16 g_hpT[KHT * OO * NN];   // h_prime transposed [kh][o][m] bf16 (4 MB)
__device__ float         g_att[KHT * NN * OO];   // attention output per (k,h)  (8 MB)
__device__ float g_thr [KHT * NN];       // -src[n]
__device__ float g_es1 [KHT * NN];       // exp(src)
__device__ float g_es2 [KHT * NN];       // exp(0.2*src)
__device__ float g_dstv[KHT * NN];       // dst[m]
__device__ float g_ed1 [KHT * NN];       // exp(dst)
__device__ float g_ed2 [KHT * NN];       // exp(0.2*dst)

// ---------------------------------------------------------------------------
// Arch-agnostic tensor-core helpers (generic PTX, works on compute_103)
// ---------------------------------------------------------------------------
__device__ __forceinline__ uint32_t smem_u32(const void* p) {
    uint32_t a;
    asm("{ .reg .u64 t; cvta.to.shared.u64 t, %1; cvt.u32.u64 %0, t; }" : "=r"(a) : "l"(p));
    return a;
}
__device__ __forceinline__ void ldsm_x4(uint32_t* r, uint32_t addr) {
    asm volatile("ldmatrix.sync.aligned.m8n8.x4.shared.b16 {%0,%1,%2,%3}, [%4];"
        : "=r"(r[0]), "=r"(r[1]), "=r"(r[2]), "=r"(r[3]) : "r"(addr));
}
__device__ __forceinline__ void mma16816(float* c, const uint32_t* a, const uint32_t* b) {
    asm volatile("mma.sync.aligned.m16n8k16.row.col.f32.bf16.bf16.f32 "
        "{%0,%1,%2,%3}, {%4,%5,%6,%7}, {%8,%9}, {%0,%1,%2,%3};"
        : "+f"(c[0]), "+f"(c[1]), "+f"(c[2]), "+f"(c[3])
        : "r"(a[0]), "r"(a[1]), "r"(a[2]), "r"(a[3]), "r"(b[0]), "r"(b[1]));
}

// ---------------------------------------------------------------------------
// Kernel 1 (fused): h_prime = h @ w  ->  bf16 transposed copy (MMA B operand)
//                   + tanh / a_src / a_dst dots + factorized exponentials.
// grid (N/64, KH), 256 threads.
// ---------------------------------------------------------------------------
__global__ void k_hproj(const float* __restrict__ h, const float* __restrict__ w,
                        const float* __restrict__ a_src, const float* __restrict__ a_dst) {
    const int kh = blockIdx.y;
    const int n0 = blockIdx.x * 64;
    __shared__ float shT[64][68];     // [d][i]  (transposed h tile)
    __shared__ float buf[64 * 68];    // first 4096 floats: w tile; reused as [o][n] (stride 68)
    __shared__ float sa[128];         // a_src[kh][o], a_dst[kh][o]
    const int tid = threadIdx.x;

    if (tid < 64) {
        sa[tid]      = a_src[kh * 64 + tid];
        sa[64 + tid] = a_dst[kh * 64 + tid];
    }

    const float4* wkh = (const float4*)(w + (size_t)kh * 64 * 64);
    #pragma unroll
    for (int it = 0; it < 4; it++) ((float4*)buf)[tid + it * 256] = wkh[tid + it * 256];

    {
        const int d = tid & 63, ig0 = tid >> 6;
        #pragma unroll
        for (int it = 0; it < 4; it++) {
            const int ig = ig0 + it * 4;
            float4 v;
            v.x = h[(size_t)(n0 + ig * 4 + 0) * DD + d];
            v.y = h[(size_t)(n0 + ig * 4 + 1) * DD + d];
            v.z = h[(size_t)(n0 + ig * 4 + 2) * DD + d];
            v.w = h[(size_t)(n0 + ig * 4 + 3) * DD + d];
            *(float4*)&shT[d][ig * 4] = v;
        }
    }
    __syncthreads();

    const int ty = tid >> 4, tx = tid & 15;
    float acc[4][4] = {};
    #pragma unroll 8
    for (int j = 0; j < 64; j++) {
        const float4 pv = *(const float4*)&shT[j][ty * 4];
        const float4 hv = *(const float4*)&buf[j * 64 + tx * 4];
        acc[0][0] += pv.x * hv.x; acc[0][1] += pv.x * hv.y; acc[0][2] += pv.x * hv.z; acc[0][3] += pv.x * hv.w;
        acc[1][0] += pv.y * hv.x; acc[1][1] += pv.y * hv.y; acc[1][2] += pv.y * hv.z; acc[1][3] += pv.y * hv.w;
        acc[2][0] += pv.z * hv.x; acc[2][1] += pv.z * hv.y; acc[2][2] += pv.z * hv.z; acc[2][3] += pv.z * hv.w;
        acc[3][0] += pv.w * hv.x; acc[3][1] += pv.w * hv.y; acc[3][2] += pv.w * hv.z; acc[3][3] += pv.w * hv.w;
    }

    // ---- fused attvec: per-row tanh-dot partials, reduce across tx ----
    {
        float pas[4] = {}, pad[4] = {};
        #pragma unroll
        for (int r = 0; r < 4; r++)
            #pragma unroll
            for (int c = 0; c < 4; c++) {
                const float t = tanhf(acc[r][c]);
                pas[r] += t * sa[tx * 4 + c];
                pad[r] += t * sa[64 + tx * 4 + c];
            }
        #pragma unroll
        for (int off = 1; off < 16; off <<= 1)
            #pragma unroll
            for (int r = 0; r < 4; r++) {
                pas[r] += __shfl_xor_sync(0xFFFFFFFFu, pas[r], off);
                pad[r] += __shfl_xor_sync(0xFFFFFFFFu, pad[r], off);
            }
        if (tx == 0) {
            #pragma unroll
            for (int r = 0; r < 4; r++) {
                const int idx = kh * NN + n0 + ty * 4 + r;
                const float as = pas[r], ad = pad[r];
                g_thr [idx] = -as;
                g_es1 [idx] = expf(as);
                g_es2 [idx] = expf(0.2f * as);
                g_dstv[idx] = ad;
                g_ed1 [idx] = expf(ad);
                g_ed2 [idx] = expf(0.2f * ad);
            }
        }
    }

    __syncthreads();            // done reading buf as w-tile
    // transpose into buf as [o][n_local], stride 68 to avoid conflicts
    #pragma unroll
    for (int r = 0; r < 4; r++)
        #pragma unroll
        for (int c = 0; c < 4; c++)
            buf[(tx * 4 + c) * 68 + ty * 4 + r] = acc[r][c];
    __syncthreads();
    // write bf16 transposed rows: thread -> row o = tid>>2, 16 n values
    {
        const int o = tid >> 2, nc = (tid & 3) * 16;
        __nv_bfloat162 tmp[8];
        #pragma unroll
        for (int j = 0; j < 8; j++)
            tmp[j] = __floats2bfloat162_rn(buf[o * 68 + nc + 2 * j], buf[o * 68 + nc + 2 * j + 1]);
        __nv_bfloat16* dst = g_hpT + ((size_t)kh * 64 + o) * NN + n0 + nc;
        *(uint4*)dst       = ((uint4*)tmp)[0];
        *(uint4*)(dst + 8) = ((uint4*)tmp)[1];
    }
}

// ---------------------------------------------------------------------------
// Kernel 2 (dominant, mma.sync bf16): ONE head per CTA, coalesced float4 adj,
// DOUBLE-BUFFERED P/B smem (1 sync per chunk), prefetch issued BEFORE the
// barrier so LDG latency hides under barrier-wait + mma phase.
//   D[128,64] += P[128,64]_bf16 @ HpT[64(o),64(m)]_bf16^T   (chunks over m)
//   P[n,m] = adj[k][n][m] * (dst[m] >= -src[n] ? es1[n]*ed1[m] : es2[n]*ed2[m])
// grid (N/128=32, K=2, H=4), 256 threads (8 warps), dynamic smem 58KB.
// Row consts packed (thr,e1,e2,pad) float4 -> 1 LDS.128 per row-group.
// ---------------------------------------------------------------------------
#define P_OFF   0
#define PH_B    18432
#define B_OFF   36864
#define BH_B    9216
#define RC_OFF  55296     // 128 rows x float4 = 2048 B
#define D_OFF   57344     // 512 B
#define SMEM_DYN 57856

__global__ void __launch_bounds__(256, 2) k_main10(const float* __restrict__ adj) {
    extern __shared__ char sm[];
    const uint32_t smb = smem_u32(sm);
    const int tid  = threadIdx.x;
    const int wid  = tid >> 5;
    const int lane = tid & 31;
    const int k    = blockIdx.y;
    const int hh   = blockIdx.z;
    const int n0   = blockIdx.x * 128;
    const int kh   = k * HH + hh;

    // stage packed row-side constants into smem: [row] = (thr, e1, e2, 0)
    if (tid < 128) {
        const int ridx = kh * NN + n0 + tid;
        float4 rc;
        rc.x = g_thr[ridx];
        rc.y = g_es1[ridx];
        rc.z = g_es2[ridx];
        rc.w = 0.0f;
        ((float4*)(sm + RC_OFF))[tid] = rc;
    }

    // P-build mapping: fixed cols, walk rows
    const int g     = tid >> 4;          // 0..15
    const int cbase = (tid & 15) * 4;    // 0..60
    const float* adjbase = adj + (size_t)k * NN * NN + (size_t)n0 * NN;
    const float* mdv = g_dstv + kh * NN;
    const float* me1 = g_ed1  + kh * NN;
    const float* me2 = g_ed2  + kh * NN;

    // B tile load mapping: 64 rows x 64 bf16 = 512 uint4, 2 per thread
    const int brow0 = tid >> 3,          bcol0 = tid & 7;
    const int brow1 = (tid + 256) >> 3,  bcol1 = tid & 7;
    const __nv_bfloat16* hptk = g_hpT + (size_t)kh * 64 * NN;

    // mma warp mapping: warp -> (row slab = wid&3, o-half = wid>>2)
    const int slab  = wid & 3;
    const int ohalf = wid >> 2;
    const int mbase = slab * 32;
    const int a_row = ((lane >> 3) & 1) * 8 + (lane & 7);
    const int a_k   = (lane >> 4) * 8;
    const uint32_t aAddr = smb + P_OFF + (mbase + a_row) * 144 + a_k * 2;
    const int b_n = ((lane >> 4) & 1) * 8 + (lane & 7);
    const int b_k = ((lane >> 3) & 1) * 8;
    const uint32_t bAddr = smb + B_OFF + (ohalf * 32 + b_n) * 144 + b_k * 2;

    float acc[2][4][4];     // [row 16-slab][o-frag][c]
    #pragma unroll
    for (int a = 0; a < 2; a++)
        #pragma unroll
        for (int b = 0; b < 4; b++)
            #pragma unroll
            for (int cc = 0; cc < 4; cc++) acc[a][b][cc] = 0.0f;
    float den[8];
    #pragma unroll
    for (int j = 0; j < 8; j++) den[j] = 0.0f;

    const float4* srcv = (const float4*)(sm + RC_OFF);

    // ---- prefetch chunk 0 ----
    float4 a4[8];
    uint4  bq0, bq1;
    float4 dv4, q14, q24;
    {
        #pragma unroll
        for (int j = 0; j < 8; j++)
            a4[j] = *(const float4*)(adjbase + (size_t)(g + j * 16) * NN + cbase);
        bq0 = *(const uint4*)(hptk + (size_t)brow0 * NN + bcol0 * 8);
        bq1 = *(const uint4*)(hptk + (size_t)brow1 * NN + bcol1 * 8);
        dv4 = *(const float4*)(mdv + cbase);
        q14 = *(const float4*)(me1 + cbase);
        q24 = *(const float4*)(me2 + cbase);
    }
    __syncthreads();   // row consts visible

    for (int c = 0; c < NN / 64; c++) {
        const int buf = c & 1;

        // ---- stage B (from prefetched regs) ----
        *(uint4*)(sm + B_OFF + buf * BH_B + brow0 * 144 + bcol0 * 16) = bq0;
        *(uint4*)(sm + B_OFF + buf * BH_B + brow1 * 144 + bcol1 * 16) = bq1;

        // ---- build P tile (bf16): 8 rows x 4 cols per thread ----
        #pragma unroll
        for (int j = 0; j < 8; j++) {
            const int row = g + j * 16;
            const float4 rc = srcv[row];     // (thr, e1, e2, -)
            const float p0 = a4[j].x * ((dv4.x >= rc.x) ? rc.y * q14.x : rc.z * q24.x);
            const float p1 = a4[j].y * ((dv4.y >= rc.x) ? rc.y * q14.y : rc.z * q24.y);
            const float p2 = a4[j].z * ((dv4.z >= rc.x) ? rc.y * q14.z : rc.z * q24.z);
            const float p3 = a4[j].w * ((dv4.w >= rc.x) ? rc.y * q14.w : rc.z * q24.w);
            den[j] += (p0 + p1) + (p2 + p3);
            __nv_bfloat162 lo = __floats2bfloat162_rn(p0, p1);
            __nv_bfloat162 hi = __floats2bfloat162_rn(p2, p3);
            uint2 v;
            v.x = *(uint32_t*)&lo;
            v.y = *(uint32_t*)&hi;
            *(uint2*)(sm + P_OFF + buf * PH_B + row * 144 + cbase * 2) = v;
        }

        // ---- prefetch chunk c+1 BEFORE the barrier (flies under sync+mma) ----
        if (c < NN / 64 - 1) {
            const int mt = (c + 1) << 6;
            #pragma unroll
            for (int j = 0; j < 8; j++)
                a4[j] = *(const float4*)(adjbase + (size_t)(g + j * 16) * NN + mt + cbase);
            bq0 = *(const uint4*)(hptk + (size_t)brow0 * NN + mt + bcol0 * 8);
            bq1 = *(const uint4*)(hptk + (size_t)brow1 * NN + mt + bcol1 * 8);
            dv4 = *(const float4*)(mdv + mt + cbase);
            q14 = *(const float4*)(me1 + mt + cbase);
            q24 = *(const float4*)(me2 + mt + cbase);
        }

        __syncthreads();   // this chunk's P + B visible; prior chunk's mma reads done

        // ---- tensor cores: 32 x m16n8k16 per warp ----
        const uint32_t aB = aAddr + buf * PH_B;
        const uint32_t bB = bAddr + buf * BH_B;
        #pragma unroll
        for (int ks = 0; ks < 4; ks++) {
            uint32_t af0[4], af1[4];
            ldsm_x4(af0, aB + ks * 32);
            ldsm_x4(af1, aB + 16 * 144 + ks * 32);
            #pragma unroll
            for (int nt = 0; nt < 2; nt++) {
                uint32_t bf[4];
                ldsm_x4(bf, bB + nt * (16 * 144) + ks * 32);
                mma16816(acc[0][2 * nt],     af0, bf);
                mma16816(acc[0][2 * nt + 1], af0, bf + 2);
                mma16816(acc[1][2 * nt],     af1, bf);
                mma16816(acc[1][2 * nt + 1], af1, bf + 2);
            }
        }
    }

    // ---- denominator reduce: 16 col-owner lanes per row ----
    #pragma unroll
    for (int j = 0; j < 8; j++) {
        float v = den[j];
        v += __shfl_xor_sync(0xFFFFFFFFu, v, 8);
        v += __shfl_xor_sync(0xFFFFFFFFu, v, 4);
        v += __shfl_xor_sync(0xFFFFFFFFu, v, 2);
        v += __shfl_xor_sync(0xFFFFFFFFu, v, 1);
        if ((tid & 15) == 0)
            ((float*)(sm + D_OFF))[g + j * 16] = v;
    }
    __syncthreads();

    // ---- epilogue: scale by 1/den, store ----
    const float* sden = (const float*)(sm + D_OFF);
    #pragma unroll
    for (int mt2 = 0; mt2 < 2; mt2++) {
        const int row0 = mbase + mt2 * 16 + (lane >> 2);
        const float inv0 = 1.0f / sden[row0];
        const float inv1 = 1.0f / sden[row0 + 8];
        float* op0 = g_att + ((size_t)kh * NN + n0 + row0) * OO;
        float* op1 = op0 + 8 * OO;
        #pragma unroll
        for (int j = 0; j < 4; j++) {
            const int col = ohalf * 32 + j * 8 + (lane & 3) * 2;
            float2 v0 = make_float2(acc[mt2][j][0] * inv0, acc[mt2][j][1] * inv0);
            float2 v1 = make_float2(acc[mt2][j][2] * inv1, acc[mt2][j][3] * inv1);
            *(float2*)(op0 + col) = v0;
            *(float2*)(op1 + col) = v1;
        }
    }
}

// ---------------------------------------------------------------------------
// Kernel 3: head-mean -> concat -> fc (C=2) -> log_softmax.
// ---------------------------------------------------------------------------
__global__ void k_final(const float* __restrict__ fc_w, const float* __restrict__ fc_b,
                        float* __restrict__ out) {
    const int wg = blockIdx.x * 8 + (threadIdx.x >> 5);
    if (wg >= NUSER) return;
    const int lane = threadIdx.x & 31;
    const int n = wg;

    float l0 = 0.0f, l1 = 0.0f;
    #pragma unroll
    for (int u = 0; u < 4; u++) {
        const int d = lane + u * 32;
        const int k = d >> 6, o = d & 63;
        float e = 0.0f;
        #pragma unroll
        for (int h = 0; h < HH; h++)
            e += g_att[(((size_t)(k * HH + h) * NN) + n) * OO + o];
        e *= 0.25f;
        l0 += e * fc_w[d];
        l1 += e * fc_w[128 + d];
    }
    #pragma unroll
    for (int off = 16; off; off >>= 1) {
        l0 += __shfl_xor_sync(0xFFFFFFFFu, l0, off);
        l1 += __shfl_xor_sync(0xFFFFFFFFu, l1, off);
    }
    if (lane == 0) {
        l0 += fc_b[0];
        l1 += fc_b[1];
        const float mx  = fmaxf(l0, l1);
        const float lse = mx + logf(expf(l0 - mx) + expf(l1 - mx));
        out[n * 2 + 0] = l0 - lse;
        out[n * 2 + 1] = l1 - lse;
    }
}

// ---------------------------------------------------------------------------
extern "C" void kernel_launch(void* const* d_in, const int* in_sizes, int n_in,
                              void* d_out, int out_size) {
    (void)in_sizes; (void)n_in; (void)out_size;
    const float* h     = (const float*)d_in[0];
    const float* hadj  = (const float*)d_in[1];
    const float* w     = (const float*)d_in[2];
    const float* a_src = (const float*)d_in[3];
    const float* a_dst = (const float*)d_in[4];
    const float* fc_w  = (const float*)d_in[5];
    const float* fc_b  = (const float*)d_in[6];
    float* out = (float*)d_out;

    static int init_done = 0;
    if (!init_done) {
        cudaFuncSetAttribute(k_main10, cudaFuncAttributeMaxDynamicSharedMemorySize, SMEM_DYN);
        init_done = 1;
    }

    k_hproj  <<<dim3(NN / 64, KHT), 256>>>(h, w, a_src, a_dst);
    k_main10 <<<dim3(NN / 128, KK, HH), 256, SMEM_DYN>>>(hadj);
    k_final  <<<NUSER / 8, 256>>>(fc_w, fc_b, out);
}

// round 16
// speedup vs baseline: 1.5826x; 1.0483x over previous
#include <cuda_runtime.h>
#include <cuda_bf16.h>
#include <math.h>
#include <stdint.h>

// Problem constants
#define NN    4096
#define DD    64
#define HH    4
#define OO    64
#define KK    2
#define KHT   8        // K*H
#define NUSER 4000
#define CC    2

// Device scratch (allocation-free rule: static __device__ arrays)
__device__ __nv_bfloat16 g_hpT[KHT * OO * NN];   // h_prime transposed [kh][o][m] bf16 (4 MB)
__device__ float         g_att[KHT * NN * OO];   // attention output per (k,h)  (8 MB)
__device__ float g_es1 [KHT * NN];       // exp(src)
__device__ float g_es2 [KHT * NN];       // exp(0.2*src)
__device__ float g_ed1 [KHT * NN];       // exp(dst)
__device__ float g_ed2 [KHT * NN];       // exp(0.2*dst)

// ---------------------------------------------------------------------------
// Arch-agnostic tensor-core / bf16x2 helpers (generic PTX, works on compute_103)
// ---------------------------------------------------------------------------
__device__ __forceinline__ uint32_t smem_u32(const void* p) {
    uint32_t a;
    asm("{ .reg .u64 t; cvta.to.shared.u64 t, %1; cvt.u32.u64 %0, t; }" : "=r"(a) : "l"(p));
    return a;
}
__device__ __forceinline__ void ldsm_x4(uint32_t* r, uint32_t addr) {
    asm volatile("ldmatrix.sync.aligned.m8n8.x4.shared.b16 {%0,%1,%2,%3}, [%4];"
        : "=r"(r[0]), "=r"(r[1]), "=r"(r[2]), "=r"(r[3]) : "r"(addr));
}
__device__ __forceinline__ void mma16816(float* c, const uint32_t* a, const uint32_t* b) {
    asm volatile("mma.sync.aligned.m16n8k16.row.col.f32.bf16.bf16.f32 "
        "{%0,%1,%2,%3}, {%4,%5,%6,%7}, {%8,%9}, {%0,%1,%2,%3};"
        : "+f"(c[0]), "+f"(c[1]), "+f"(c[2]), "+f"(c[3])
        : "r"(a[0]), "r"(a[1]), "r"(a[2]), "r"(a[3]), "r"(b[0]), "r"(b[1]));
}
// pack (lo, hi) fp32 -> bf16x2
__device__ __forceinline__ uint32_t cvt_bf2(float lo, float hi) {
    uint32_t r;
    asm("cvt.rn.bf16x2.f32 %0, %1, %2;" : "=r"(r) : "f"(hi), "f"(lo));
    return r;
}
__device__ __forceinline__ uint32_t mul_bf2(uint32_t a, uint32_t b) {
    uint32_t r;
    asm("mul.rn.bf16x2 %0, %1, %2;" : "=r"(r) : "r"(a), "r"(b));
    return r;
}
__device__ __forceinline__ uint32_t max_bf2(uint32_t a, uint32_t b) {
    uint32_t r;
    asm("max.bf16x2 %0, %1, %2;" : "=r"(r) : "r"(a), "r"(b));
    return r;
}

// ---------------------------------------------------------------------------
// Kernel 1 (fused): h_prime = h @ w  ->  bf16 transposed copy (MMA B operand)
//                   + tanh / a_src / a_dst dots + factorized exponentials.
// grid (N/64, KH), 256 threads.
// ---------------------------------------------------------------------------
__global__ void k_hproj(const float* __restrict__ h, const float* __restrict__ w,
                        const float* __restrict__ a_src, const float* __restrict__ a_dst) {
    const int kh = blockIdx.y;
    const int n0 = blockIdx.x * 64;
    __shared__ float shT[64][68];     // [d][i]  (transposed h tile)
    __shared__ float buf[64 * 68];    // first 4096 floats: w tile; reused as [o][n] (stride 68)
    __shared__ float sa[128];         // a_src[kh][o], a_dst[kh][o]
    const int tid = threadIdx.x;

    if (tid < 64) {
        sa[tid]      = a_src[kh * 64 + tid];
        sa[64 + tid] = a_dst[kh * 64 + tid];
    }

    const float4* wkh = (const float4*)(w + (size_t)kh * 64 * 64);
    #pragma unroll
    for (int it = 0; it < 4; it++) ((float4*)buf)[tid + it * 256] = wkh[tid + it * 256];

    {
        const int d = tid & 63, ig0 = tid >> 6;
        #pragma unroll
        for (int it = 0; it < 4; it++) {
            const int ig = ig0 + it * 4;
            float4 v;
            v.x = h[(size_t)(n0 + ig * 4 + 0) * DD + d];
            v.y = h[(size_t)(n0 + ig * 4 + 1) * DD + d];
            v.z = h[(size_t)(n0 + ig * 4 + 2) * DD + d];
            v.w = h[(size_t)(n0 + ig * 4 + 3) * DD + d];
            *(float4*)&shT[d][ig * 4] = v;
        }
    }
    __syncthreads();

    const int ty = tid >> 4, tx = tid & 15;
    float acc[4][4] = {};
    #pragma unroll 8
    for (int j = 0; j < 64; j++) {
        const float4 pv = *(const float4*)&shT[j][ty * 4];
        const float4 hv = *(const float4*)&buf[j * 64 + tx * 4];
        acc[0][0] += pv.x * hv.x; acc[0][1] += pv.x * hv.y; acc[0][2] += pv.x * hv.z; acc[0][3] += pv.x * hv.w;
        acc[1][0] += pv.y * hv.x; acc[1][1] += pv.y * hv.y; acc[1][2] += pv.y * hv.z; acc[1][3] += pv.y * hv.w;
        acc[2][0] += pv.z * hv.x; acc[2][1] += pv.z * hv.y; acc[2][2] += pv.z * hv.z; acc[2][3] += pv.z * hv.w;
        acc[3][0] += pv.w * hv.x; acc[3][1] += pv.w * hv.y; acc[3][2] += pv.w * hv.z; acc[3][3] += pv.w * hv.w;
    }

    // ---- fused attvec: per-row tanh-dot partials, reduce across tx ----
    {
        float pas[4] = {}, pad[4] = {};
        #pragma unroll
        for (int r = 0; r < 4; r++)
            #pragma unroll
            for (int c = 0; c < 4; c++) {
                const float t = tanhf(acc[r][c]);
                pas[r] += t * sa[tx * 4 + c];
                pad[r] += t * sa[64 + tx * 4 + c];
            }
        #pragma unroll
        for (int off = 1; off < 16; off <<= 1)
            #pragma unroll
            for (int r = 0; r < 4; r++) {
                pas[r] += __shfl_xor_sync(0xFFFFFFFFu, pas[r], off);
                pad[r] += __shfl_xor_sync(0xFFFFFFFFu, pad[r], off);
            }
        if (tx == 0) {
            #pragma unroll
            for (int r = 0; r < 4; r++) {
                const int idx = kh * NN + n0 + ty * 4 + r;
                const float as = pas[r], ad = pad[r];
                g_es1 [idx] = expf(as);
                g_es2 [idx] = expf(0.2f * as);
                g_ed1 [idx] = expf(ad);
                g_ed2 [idx] = expf(0.2f * ad);
            }
        }
    }

    __syncthreads();            // done reading buf as w-tile
    // transpose into buf as [o][n_local], stride 68 to avoid conflicts
    #pragma unroll
    for (int r = 0; r < 4; r++)
        #pragma unroll
        for (int c = 0; c < 4; c++)
            buf[(tx * 4 + c) * 68 + ty * 4 + r] = acc[r][c];
    __syncthreads();
    // write bf16 transposed rows: thread -> row o = tid>>2, 16 n values
    {
        const int o = tid >> 2, nc = (tid & 3) * 16;
        __nv_bfloat162 tmp[8];
        #pragma unroll
        for (int j = 0; j < 8; j++)
            tmp[j] = __floats2bfloat162_rn(buf[o * 68 + nc + 2 * j], buf[o * 68 + nc + 2 * j + 1]);
        __nv_bfloat16* dst = g_hpT + ((size_t)kh * 64 + o) * NN + n0 + nc;
        *(uint4*)dst       = ((uint4*)tmp)[0];
        *(uint4*)(dst + 8) = ((uint4*)tmp)[1];
    }
}

// ---------------------------------------------------------------------------
// Kernel 2 (dominant, mma.sync bf16): ONE head per CTA, coalesced float4 adj,
// double-buffered P/B smem, prefetch before barrier, bf16x2 P-build:
//   P[n,m] = adj * max(e1[n]*q1[m], e2[n]*q2[m])   (exp(leaky) = max of exps)
// den computed by the MMA itself: B row 64 = ones -> accumulator col 64.
// grid (N/128=32, K=2, H=4), 256 threads (8 warps), dynamic smem 60KB.
// ---------------------------------------------------------------------------
#define P_OFF   0
#define PH_B    18432            // 128 rows x 144B
#define B_OFF   36864
#define BH_B    11520            // 80 rows x 144B (64 data + ones row 64 + zeros)
#define RC_OFF  59904            // e1 splat pairs 512B, e2 splat pairs 512B
#define D_OFF   60928            // 512B den
#define SMEM_DYN 61440

__global__ void __launch_bounds__(256, 2) k_main11(const float* __restrict__ adj) {
    extern __shared__ char sm[];
    const uint32_t smb = smem_u32(sm);
    const int tid  = threadIdx.x;
    const int wid  = tid >> 5;
    const int lane = tid & 31;
    const int k    = blockIdx.y;
    const int hh   = blockIdx.z;
    const int n0   = blockIdx.x * 128;
    const int kh   = k * HH + hh;

    // ---- prologue: row-side exp splat pairs (bf16x2) ----
    if (tid < 128) {
        const int ridx = kh * NN + n0 + tid;
        const float e1 = g_es1[ridx];
        const float e2 = g_es2[ridx];
        ((uint32_t*)(sm + RC_OFF))[tid]       = cvt_bf2(e1, e1);
        ((uint32_t*)(sm + RC_OFF + 512))[tid] = cvt_bf2(e2, e2);
    }
    // ---- prologue: B rows 64..79 for both buffers (row 64 = ones, rest 0) ----
    {
        const int bsel = tid >> 7;             // buffer 0/1
        const int rem  = tid & 127;
        const int row  = 64 + (rem >> 3);      // 64..79
        const int c16  = rem & 7;              // 16B column
        const uint32_t ones = 0x3F803F80u;     // bf16 1.0 pair
        uint4 v = (row == 64) ? make_uint4(ones, ones, ones, ones)
                              : make_uint4(0u, 0u, 0u, 0u);
        *(uint4*)(sm + B_OFF + bsel * BH_B + row * 144 + c16 * 16) = v;
    }

    // P-build mapping: fixed cols, walk rows
    const int g     = tid >> 4;          // 0..15
    const int cbase = (tid & 15) * 4;    // 0..60
    const float* adjbase = adj + (size_t)k * NN * NN + (size_t)n0 * NN;
    const float* me1 = g_ed1 + kh * NN;
    const float* me2 = g_ed2 + kh * NN;

    // B tile load mapping: 64 rows x 64 bf16 = 512 uint4, 2 per thread
    const int brow0 = tid >> 3,          bcol0 = tid & 7;
    const int brow1 = (tid + 256) >> 3,  bcol1 = tid & 7;
    const __nv_bfloat16* hptk = g_hpT + (size_t)kh * 64 * NN;

    // mma warp mapping: warp -> (row slab = wid&3, o-half = wid>>2)
    const int slab  = wid & 3;
    const int ohalf = wid >> 2;
    const int mbase = slab * 32;
    const int a_row = ((lane >> 3) & 1) * 8 + (lane & 7);
    const int a_k   = (lane >> 4) * 8;
    const uint32_t aAddr = smb + P_OFF + (mbase + a_row) * 144 + a_k * 2;
    const int b_n = ((lane >> 4) & 1) * 8 + (lane & 7);
    const int b_k = ((lane >> 3) & 1) * 8;
    const uint32_t bAddr  = smb + B_OFF + (ohalf * 32 + b_n) * 144 + b_k * 2;
    const uint32_t bAddrE = smb + B_OFF + (64 + b_n) * 144 + b_k * 2;   // ones-row frag

    float acc[2][4][4];     // [row 16-slab][o-frag][c]
    float accE[2][4];       // ones-column (den) accumulator, ohalf==1 warps
    #pragma unroll
    for (int a = 0; a < 2; a++) {
        #pragma unroll
        for (int b = 0; b < 4; b++) {
            #pragma unroll
            for (int cc = 0; cc < 4; cc++) acc[a][b][cc] = 0.0f;
            accE[a][b] = 0.0f;
        }
    }

    const uint32_t* sE1 = (const uint32_t*)(sm + RC_OFF);
    const uint32_t* sE2 = (const uint32_t*)(sm + RC_OFF + 512);

    // ---- prefetch chunk 0 ----
    float4 a4[8];
    uint4  bq0, bq1;
    float4 q14, q24;
    {
        #pragma unroll
        for (int j = 0; j < 8; j++)
            a4[j] = *(const float4*)(adjbase + (size_t)(g + j * 16) * NN + cbase);
        bq0 = *(const uint4*)(hptk + (size_t)brow0 * NN + bcol0 * 8);
        bq1 = *(const uint4*)(hptk + (size_t)brow1 * NN + bcol1 * 8);
        q14 = *(const float4*)(me1 + cbase);
        q24 = *(const float4*)(me2 + cbase);
    }
    __syncthreads();   // prologue (RC + ones rows) visible

    for (int c = 0; c < NN / 64; c++) {
        const int buf = c & 1;

        // ---- stage B (from prefetched regs) ----
        *(uint4*)(sm + B_OFF + buf * BH_B + brow0 * 144 + bcol0 * 16) = bq0;
        *(uint4*)(sm + B_OFF + buf * BH_B + brow1 * 144 + bcol1 * 16) = bq1;

        // ---- convert m-side exps to splat-free bf16x2 pairs ----
        const uint32_t q1p0 = cvt_bf2(q14.x, q14.y);
        const uint32_t q1p1 = cvt_bf2(q14.z, q14.w);
        const uint32_t q2p0 = cvt_bf2(q24.x, q24.y);
        const uint32_t q2p1 = cvt_bf2(q24.z, q24.w);

        // ---- build P tile (bf16x2): 8 rows x 4 cols per thread ----
        #pragma unroll
        for (int j = 0; j < 8; j++) {
            const int row = g + j * 16;
            const uint32_t e1p = sE1[row];
            const uint32_t e2p = sE2[row];
            const uint32_t m0 = max_bf2(mul_bf2(e1p, q1p0), mul_bf2(e2p, q2p0));
            const uint32_t m1 = max_bf2(mul_bf2(e1p, q1p1), mul_bf2(e2p, q2p1));
            const uint32_t ap0 = cvt_bf2(a4[j].x, a4[j].y);
            const uint32_t ap1 = cvt_bf2(a4[j].z, a4[j].w);
            uint2 v;
            v.x = mul_bf2(m0, ap0);
            v.y = mul_bf2(m1, ap1);
            *(uint2*)(sm + P_OFF + buf * PH_B + row * 144 + cbase * 2) = v;
        }

        // ---- prefetch chunk c+1 BEFORE the barrier (flies under sync+mma) ----
        if (c < NN / 64 - 1) {
            const int mt = (c + 1) << 6;
            #pragma unroll
            for (int j = 0; j < 8; j++)
                a4[j] = *(const float4*)(adjbase + (size_t)(g + j * 16) * NN + mt + cbase);
            bq0 = *(const uint4*)(hptk + (size_t)brow0 * NN + mt + bcol0 * 8);
            bq1 = *(const uint4*)(hptk + (size_t)brow1 * NN + mt + bcol1 * 8);
            q14 = *(const float4*)(me1 + mt + cbase);
            q24 = *(const float4*)(me2 + mt + cbase);
        }

        __syncthreads();   // this chunk's P + B visible; prior chunk's mma reads done

        // ---- tensor cores: 32 (+8 den) x m16n8k16 per warp ----
        const uint32_t aB = aAddr + buf * PH_B;
        const uint32_t bB = bAddr + buf * BH_B;
        const uint32_t bE = bAddrE + buf * BH_B;
        #pragma unroll
        for (int ks = 0; ks < 4; ks++) {
            uint32_t af0[4], af1[4];
            ldsm_x4(af0, aB + ks * 32);
            ldsm_x4(af1, aB + 16 * 144 + ks * 32);
            #pragma unroll
            for (int nt = 0; nt < 2; nt++) {
                uint32_t bf[4];
                ldsm_x4(bf, bB + nt * (16 * 144) + ks * 32);
                mma16816(acc[0][2 * nt],     af0, bf);
                mma16816(acc[0][2 * nt + 1], af0, bf + 2);
                mma16816(acc[1][2 * nt],     af1, bf);
                mma16816(acc[1][2 * nt + 1], af1, bf + 2);
            }
            if (ohalf) {
                uint32_t bfE[4];
                ldsm_x4(bfE, bE + ks * 32);
                mma16816(accE[0], af0, bfE);
                mma16816(accE[1], af1, bfE);
            }
        }
    }

    // ---- den: ones-column of accumulator (n=64 -> lanes lane%4==0, c0/c2) ----
    if (ohalf) {
        #pragma unroll
        for (int mt2 = 0; mt2 < 2; mt2++) {
            const int row0 = mbase + mt2 * 16 + (lane >> 2);
            if ((lane & 3) == 0) {
                ((float*)(sm + D_OFF))[row0]     = accE[mt2][0];
                ((float*)(sm + D_OFF))[row0 + 8] = accE[mt2][2];
            }
        }
    }
    __syncthreads();

    // ---- epilogue: scale by 1/den, store ----
    const float* sden = (const float*)(sm + D_OFF);
    #pragma unroll
    for (int mt2 = 0; mt2 < 2; mt2++) {
        const int row0 = mbase + mt2 * 16 + (lane >> 2);
        const float inv0 = 1.0f / sden[row0];
        const float inv1 = 1.0f / sden[row0 + 8];
        float* op0 = g_att + ((size_t)kh * NN + n0 + row0) * OO;
        float* op1 = op0 + 8 * OO;
        #pragma unroll
        for (int j = 0; j < 4; j++) {
            const int col = ohalf * 32 + j * 8 + (lane & 3) * 2;
            float2 v0 = make_float2(acc[mt2][j][0] * inv0, acc[mt2][j][1] * inv0);
            float2 v1 = make_float2(acc[mt2][j][2] * inv1, acc[mt2][j][3] * inv1);
            *(float2*)(op0 + col) = v0;
            *(float2*)(op1 + col) = v1;
        }
    }
}

// ---------------------------------------------------------------------------
// Kernel 3: head-mean -> concat -> fc (C=2) -> log_softmax.
// ---------------------------------------------------------------------------
__global__ void k_final(const float* __restrict__ fc_w, const float* __restrict__ fc_b,
                        float* __restrict__ out) {
    const int wg = blockIdx.x * 8 + (threadIdx.x >> 5);
    if (wg >= NUSER) return;
    const int lane = threadIdx.x & 31;
    const int n = wg;

    float l0 = 0.0f, l1 = 0.0f;
    #pragma unroll
    for (int u = 0; u < 4; u++) {
        const int d = lane + u * 32;
        const int k = d >> 6, o = d & 63;
        float e = 0.0f;
        #pragma unroll
        for (int h = 0; h < HH; h++)
            e += g_att[(((size_t)(k * HH + h) * NN) + n) * OO + o];
        e *= 0.25f;
        l0 += e * fc_w[d];
        l1 += e * fc_w[128 + d];
    }
    #pragma unroll
    for (int off = 16; off; off >>= 1) {
        l0 += __shfl_xor_sync(0xFFFFFFFFu, l0, off);
        l1 += __shfl_xor_sync(0xFFFFFFFFu, l1, off);
    }
    if (lane == 0) {
        l0 += fc_b[0];
        l1 += fc_b[1];
        const float mx  = fmaxf(l0, l1);
        const float lse = mx + logf(expf(l0 - mx) + expf(l1 - mx));
        out[n * 2 + 0] = l0 - lse;
        out[n * 2 + 1] = l1 - lse;
    }
}

// ---------------------------------------------------------------------------
extern "C" void kernel_launch(void* const* d_in, const int* in_sizes, int n_in,
                              void* d_out, int out_size) {
    (void)in_sizes; (void)n_in; (void)out_size;
    const float* h     = (const float*)d_in[0];
    const float* hadj  = (const float*)d_in[1];
    const float* w     = (const float*)d_in[2];
    const float* a_src = (const float*)d_in[3];
    const float* a_dst = (const float*)d_in[4];
    const float* fc_w  = (const float*)d_in[5];
    const float* fc_b  = (const float*)d_in[6];
    float* out = (float*)d_out;

    static int init_done = 0;
    if (!init_done) {
        cudaFuncSetAttribute(k_main11, cudaFuncAttributeMaxDynamicSharedMemorySize, SMEM_DYN);
        init_done = 1;
    }

    k_hproj  <<<dim3(NN / 64, KHT), 256>>>(h, w, a_src, a_dst);
    k_main11 <<<dim3(NN / 128, KK, HH), 256, SMEM_DYN>>>(hadj);
    k_final  <<<NUSER / 8, 256>>>(fc_w, fc_b, out);
}